// round 7
// baseline (speedup 1.0000x reference)
#include <cuda_runtime.h>
#include <cuda_bf16.h>
#include <math.h>
#include <stdint.h>

#define N_SEG 12800
#define D_ 128
#define S_ 100
#define B_ 16
#define M_ 8
#define P_ 40
#define OUT_ELEMS (S_*B_*M_*D_)   // 1638400
#define FULLMASK 0xffffffffu

#define LDT 136                    // padded bf16 row stride
#define TILE_E (128*LDT)           // 128-row tile elems
#define BTILE_B (TILE_E*2)         // 34816 bytes

// ---------------- folded weights + weight scratch ----------------
__device__ float g_score_w[24];     // [a*8+h]
__device__ float g_score_c[8];
__device__ float g_W2[24*128];      // [(h*3+a)*128 + j]
__device__ float g_c2[128];
__device__ float g_emb[N_SEG*D_];   // post-LN1 embeddings (6.5MB scratch)
// pre-split bf16 weight tiles [n][LDT]; pair w: [hi,lo]. w=0..2: w1 n-chunks, 3..5: w2 k-chunks
__device__ __align__(16) __nv_bfloat16 g_wb[6*2*TILE_E];

__device__ __forceinline__ unsigned pk2(float a, float b) {
    __nv_bfloat162 t = __floats2bfloat162_rn(a, b);
    return *reinterpret_cast<unsigned*>(&t);
}
__device__ __forceinline__ float blo(float x) {
    return x - __bfloat162float(__float2bfloat16(x));
}
__device__ __forceinline__ void mma16816(float* c, const uint32_t* a, uint32_t b0, uint32_t b1) {
    asm volatile("mma.sync.aligned.m16n8k16.row.col.f32.bf16.bf16.f32 "
        "{%0,%1,%2,%3}, {%4,%5,%6,%7}, {%8,%9}, {%0,%1,%2,%3};"
        : "+f"(c[0]), "+f"(c[1]), "+f"(c[2]), "+f"(c[3])
        : "r"(a[0]), "r"(a[1]), "r"(a[2]), "r"(a[3]), "r"(b0), "r"(b1));
}
__device__ __forceinline__ void ldsm4(uint32_t* r, uint32_t addr) {
    asm volatile("ldmatrix.sync.aligned.m8n8.x4.shared.b16 {%0,%1,%2,%3}, [%4];"
        : "=r"(r[0]), "=r"(r[1]), "=r"(r[2]), "=r"(r[3]) : "r"(addr));
}
__device__ __forceinline__ void cpa16(uint32_t daddr, const void* g) {
    asm volatile("cp.async.cg.shared.global [%0], [%1], 16;" :: "r"(daddr), "l"(g));
}
__device__ __forceinline__ void cpa_commit() {
    asm volatile("cp.async.commit_group;" ::: "memory");
}
template<int N> __device__ __forceinline__ void cpa_waitg() {
    asm volatile("cp.async.wait_group %0;" :: "n"(N) : "memory");
}

// ================= kernel 1: fold + split + raw seg flags (107 blocks) =================
#define PRE_DSMEM (192*1024)

__global__ void k_pre(const float* __restrict__ roads,
                      const float* __restrict__ ms,   const float* __restrict__ lin_w,
                      const float* __restrict__ lin_b,const float* __restrict__ wq,
                      const float* __restrict__ wk,   const float* __restrict__ wv,
                      const float* __restrict__ bq,   const float* __restrict__ bk,
                      const float* __restrict__ bv,   const float* __restrict__ out_w,
                      const float* __restrict__ out_b,
                      const float* __restrict__ w1,   const float* __restrict__ w2,
                      float* __restrict__ d_out)
{
    const int t = threadIdx.x;
    if (blockIdx.x < 6) {
        const int w = blockIdx.x;
        __nv_bfloat16* dh = g_wb + (w*2+0)*TILE_E;
        __nv_bfloat16* dl = g_wb + (w*2+1)*TILE_E;
        for (int i = t; i < 128*32; i += 256) {
            int n = i >> 5, k4 = (i & 31) << 2;
            float4 v = (w < 3)
                ? make_float4(w1[(k4+0)*384 + w*128 + n], w1[(k4+1)*384 + w*128 + n],
                              w1[(k4+2)*384 + w*128 + n], w1[(k4+3)*384 + w*128 + n])
                : make_float4(w2[((w-3)*128 + k4+0)*128 + n], w2[((w-3)*128 + k4+1)*128 + n],
                              w2[((w-3)*128 + k4+2)*128 + n], w2[((w-3)*128 + k4+3)*128 + n]);
            __nv_bfloat16 h0 = __float2bfloat16(v.x), h1 = __float2bfloat16(v.y);
            __nv_bfloat16 h2 = __float2bfloat16(v.z), h3 = __float2bfloat16(v.w);
            int off = n*LDT + k4;
            *reinterpret_cast<uint2*>(dh + off) = make_uint2(
                (uint32_t)*(uint16_t*)&h0 | ((uint32_t)*(uint16_t*)&h1 << 16),
                (uint32_t)*(uint16_t*)&h2 | ((uint32_t)*(uint16_t*)&h3 << 16));
            *reinterpret_cast<uint2*>(dl + off) = make_uint2(
                pk2(v.x - __bfloat162float(h0), v.y - __bfloat162float(h1)),
                pk2(v.z - __bfloat162float(h2), v.w - __bfloat162float(h3)));
        }
        return;
    }
    if (blockIdx.x >= 7) {
        if (t < 128) {
            const int n = (blockIdx.x - 7)*128 + t;
            const float* wp = roads + n*(P_*4) + 3;
            float sum = 0.f;
            #pragma unroll 8
            for (int p = 0; p < P_; p++) sum += wp[p*4];
            d_out[OUT_ELEMS + n] = (sum == 0.0f) ? 1.0f : 0.0f;
        }
        return;
    }

    // -------- block 6: fold attention weights (cp.async pipelined) --------
    extern __shared__ float W[];    // 3 x 16384 floats
    float* W0 = W;
    float* W1 = W + 16384;
    float* Wv = W + 32768;
    __shared__ float q[128];
    __shared__ float wkq[128*8];
    __shared__ float lwv[3*128];
    __shared__ float cv[128];
    __shared__ float ms_s[128], lb_s[128];

    const uint32_t wsb = (uint32_t)__cvta_generic_to_shared(W);
    if (t < 128) { ms_s[t] = ms[t]; lb_s[t] = lin_b[t]; }

    for (int i = t; i < 4096; i += 256) cpa16(wsb + i*16, (const char*)wq + i*16);
    cpa_commit();
    for (int i = t; i < 4096; i += 256) cpa16(wsb + 65536 + i*16, (const char*)wk + i*16);
    cpa_commit();
    for (int i = t; i < 4096; i += 256) cpa16(wsb + 131072 + i*16, (const char*)wv + i*16);
    cpa_commit();

    cpa_waitg<2>();
    __syncthreads();
    if (t < 128) {
        float acc = bq[t];
        #pragma unroll 8
        for (int e = 0; e < 128; e++) acc += ms_s[e]*W0[e*128+t];
        q[t] = acc;
    }
    __syncthreads();

    for (int i = t; i < 4096; i += 256) cpa16(wsb + i*16, (const char*)out_w + i*16);
    cpa_commit();

    cpa_waitg<2>();
    __syncthreads();
    if (t < 128) {
        #pragma unroll
        for (int h = 0; h < 8; h++) {
            float s = 0.f;
            #pragma unroll
            for (int j = 0; j < 16; j++) s += W1[t*128 + h*16 + j]*q[h*16 + j];
            wkq[t*8 + h] = s;
        }
    }
    __syncthreads();

    if (t < 24) {
        int a = t/8, h = t%8;
        float s = 0.f;
        #pragma unroll 8
        for (int d = 0; d < 128; d++) s += lin_w[a*128+d]*wkq[d*8+h];
        g_score_w[a*8+h] = 0.25f*s;
    } else if (t < 32) {
        int h = t-24;
        float s = 0.f;
        #pragma unroll 8
        for (int d = 0; d < 128; d++) s += lb_s[d]*wkq[d*8+h];
        #pragma unroll
        for (int j = 0; j < 16; j++) s += q[h*16+j]*bk[h*16+j];
        g_score_c[h] = 0.25f*s;
    }

    cpa_waitg<1>();
    __syncthreads();
    if (t < 128) {
        float s0=0.f, s1=0.f, s2=0.f, sc=0.f;
        #pragma unroll 8
        for (int e = 0; e < 128; e++) {
            float w = Wv[e*128 + t];
            s0 += lin_w[0*128+e]*w;
            s1 += lin_w[1*128+e]*w;
            s2 += lin_w[2*128+e]*w;
            sc += lb_s[e]*w;
        }
        lwv[0*128+t]=s0; lwv[1*128+t]=s1; lwv[2*128+t]=s2;
        cv[t] = sc + bv[t];
    }
    cpa_waitg<0>();
    __syncthreads();
    if (t < 128) {
        #pragma unroll
        for (int h = 0; h < 8; h++)
            #pragma unroll
            for (int a = 0; a < 3; a++) {
                float s = 0.f;
                #pragma unroll
                for (int dd = 0; dd < 16; dd++) {
                    int d = h*16 + dd;
                    s += lwv[a*128+d]*W0[d*128+t];
                }
                g_W2[(h*3+a)*128 + t] = s;
            }
        float s = out_b[t];
        #pragma unroll 8
        for (int d = 0; d < 128; d++) s += cv[d]*W0[d*128+t];
        g_c2[t] = s;
    }
}

// ================= kernel 2: attention pooling + LN1 (4 segs/warp) =================
__global__ __launch_bounds__(256)
void k_attn(const float* __restrict__ roads,
            const float* __restrict__ ln1_g, const float* __restrict__ ln1_b)
{
    __shared__ float sW2[24*128];
    __shared__ float sc2[128], sg[128], sb_[128];
    const int tid = threadIdx.x;
    for (int i = tid; i < 24*128; i += 256) sW2[i] = g_W2[i];
    if (tid < 128) { sc2[tid] = g_c2[tid]; sg[tid] = ln1_g[tid]; sb_[tid] = ln1_b[tid]; }
    __syncthreads();

    const int wid  = tid >> 5;
    const int lane = tid & 31;

    #pragma unroll
    for (int seg = 0; seg < 4; seg++) {
        const int n = (blockIdx.x*8 + wid)*4 + seg;

        const float4* rp = reinterpret_cast<const float4*>(roads) + n*P_;
        float4 a0 = rp[lane];
        float4 a1 = make_float4(0.f,0.f,0.f,0.f);
        if (lane < 8) a1 = rp[32 + lane];

        bool v0 = (a0.w != 0.0f);
        bool v1 = (lane < 8) && (a1.w != 0.0f);
        unsigned bm0 = __ballot_sync(FULLMASK, v0);
        unsigned bm1 = __ballot_sync(FULLMASK, v1);
        if (((bm0 | bm1) == 0u) && lane == 0) v0 = true;

        float pa[24];
        #pragma unroll
        for (int h = 0; h < 8; h++) {
            const float sw0 = __ldg(&g_score_w[0*8+h]);
            const float sw1 = __ldg(&g_score_w[1*8+h]);
            const float sw2 = __ldg(&g_score_w[2*8+h]);
            const float sc  = __ldg(&g_score_c[h]);
            float s0 = sc + a0.x*sw0 + a0.y*sw1 + a0.z*sw2;
            float s1 = sc + a1.x*sw0 + a1.y*sw1 + a1.z*sw2;
            float mx = fmaxf(v0 ? s0 : -1e30f, v1 ? s1 : -1e30f);
            #pragma unroll
            for (int o = 16; o; o >>= 1) mx = fmaxf(mx, __shfl_xor_sync(FULLMASK, mx, o));
            float e0 = v0 ? __expf(s0 - mx) : 0.0f;
            float e1 = v1 ? __expf(s1 - mx) : 0.0f;
            float t0 = e0 + e1;
            float t1 = e0*a0.x + e1*a1.x;
            float t2 = e0*a0.y + e1*a1.y;
            float t3 = e0*a0.z + e1*a1.z;
            #pragma unroll
            for (int o = 16; o; o >>= 1) {
                t0 += __shfl_xor_sync(FULLMASK, t0, o);
                t1 += __shfl_xor_sync(FULLMASK, t1, o);
                t2 += __shfl_xor_sync(FULLMASK, t2, o);
                t3 += __shfl_xor_sync(FULLMASK, t3, o);
            }
            float inv = 1.0f / t0;
            pa[h*3+0] = t1*inv;
            pa[h*3+1] = t2*inv;
            pa[h*3+2] = t3*inv;
        }

        float y[4];
        #pragma unroll
        for (int u = 0; u < 4; u++) {
            int j = lane + 32*u;
            float acc = sc2[j];
            #pragma unroll
            for (int i = 0; i < 24; i++) acc += pa[i]*sW2[i*128 + j];
            y[u] = acc;
        }

        float loc = y[0]+y[1]+y[2]+y[3];
        #pragma unroll
        for (int o = 16; o; o >>= 1) loc += __shfl_xor_sync(FULLMASK, loc, o);
        const float mu = loc * (1.0f/128.0f);
        float sq = 0.f;
        #pragma unroll
        for (int u = 0; u < 4; u++) { float d = y[u]-mu; sq += d*d; }
        #pragma unroll
        for (int o = 16; o; o >>= 1) sq += __shfl_xor_sync(FULLMASK, sq, o);
        const float istd = rsqrtf(sq*(1.0f/128.0f) + 1e-5f);
        #pragma unroll
        for (int u = 0; u < 4; u++) {
            int j = lane + 32*u;
            g_emb[n*128 + j] = (y[u]-mu)*istd*sg[j] + sb_[j];
        }
    }
}

// ================= kernel 3: HMMA FFN, 512 thr / 16 warps, grid 100 =================
// smem: AH | AL | HH | HL | BH | BL   (6 x 34816 = 208896 B)
#define K3_DSMEM (6*BTILE_B)

// gemm pass (warp tile m32 x n32): acc[2][4][4] += A * Bt^T
__device__ __forceinline__ void gemm_pass(uint32_t aB, uint32_t bB, float (&acc)[2][4][4])
{
    #pragma unroll
    for (int k = 0; k < 8; k++) {
        uint32_t a0[4], a1[4];
        ldsm4(a0, aB + k*32);
        ldsm4(a1, aB + 16*LDT*2 + k*32);
        #pragma unroll
        for (int ntp = 0; ntp < 2; ntp++) {
            uint32_t b[4];
            ldsm4(b, bB + ntp*16*LDT*2 + k*32);
            mma16816(acc[0][2*ntp+0], a0, b[0], b[1]);
            mma16816(acc[1][2*ntp+0], a1, b[0], b[1]);
            mma16816(acc[0][2*ntp+1], a0, b[2], b[3]);
            mma16816(acc[1][2*ntp+1], a1, b[2], b[3]);
        }
    }
}

__global__ __launch_bounds__(512, 1)
void k_ffn(const float* __restrict__ b1, const float* __restrict__ b2,
           const float* __restrict__ ln2_g, const float* __restrict__ ln2_b,
           float* __restrict__ d_out)
{
    extern __shared__ __align__(16) char smem[];
    __nv_bfloat16* sAh = reinterpret_cast<__nv_bfloat16*>(smem);
    __nv_bfloat16* sAl = sAh + TILE_E;
    __nv_bfloat16* sHh = sAl + TILE_E;
    __nv_bfloat16* sHl = sHh + TILE_E;

    const uint32_t sb = (uint32_t)__cvta_generic_to_shared(smem);
    const uint32_t AH = sb, AL = AH + BTILE_B, HH = AL + BTILE_B,
                   HL = HH + BTILE_B, BH = HL + BTILE_B;

    const int tid  = threadIdx.x;
    const int wid  = tid >> 5;          // 0..15
    const int lane = tid & 31;
    const int qr   = lane >> 2;
    const int qc   = (lane & 3) << 1;
    const int mbase = (wid & 3) * 32;
    const int nbase = (wid >> 2) * 32;
    const int base  = blockIdx.x * 128;

    const uint32_t aoff = (uint32_t)(((lane & 15)*LDT + (lane >> 4)*8)*2 + mbase*LDT*2);
    const uint32_t boff = (uint32_t)((((lane & 7) + ((lane >> 4) << 3))*LDT
                                      + ((lane >> 3) & 1)*8)*2 + nbase*LDT*2);

    // stage W1(0)
    {
        const char* src = reinterpret_cast<const char*>(g_wb);
        for (int i = tid; i < 2*BTILE_B/16; i += 512) cpa16(BH + i*16, src + i*16);
        cpa_commit();
    }

    // block 0: seg_mask all_seg fix (flags written by k_pre)
    if (blockIdx.x == 0 && tid < 128) {
        float allm = 1.0f;
        #pragma unroll 4
        for (int s = 0; s < S_; s++)
            allm = fminf(allm, d_out[OUT_ELEMS + tid*S_ + s]);
        if (allm > 0.5f) d_out[OUT_ELEMS + tid*S_] = 0.0f;
    }

    // stage A = emb tile (bf16 hi/lo)
    {
        const float4* eb = reinterpret_cast<const float4*>(g_emb + base*128);
        for (int i = tid; i < 4096; i += 512) {
            int r = i >> 5, c4 = (i & 31) << 2;
            float4 v = eb[i];
            int off = r*LDT + c4;
            *reinterpret_cast<uint2*>(sAh + off) = make_uint2(pk2(v.x,v.y), pk2(v.z,v.w));
            *reinterpret_cast<uint2*>(sAl + off) =
                make_uint2(pk2(blo(v.x),blo(v.y)), pk2(blo(v.z),blo(v.w)));
        }
    }
    cpa_waitg<0>();
    __syncthreads();

    float acc2[2][4][4];
    #pragma unroll
    for (int mt = 0; mt < 2; mt++)
        #pragma unroll
        for (int nt = 0; nt < 4; nt++)
            #pragma unroll
            for (int c = 0; c < 4; c++) acc2[mt][nt][c] = 0.f;

    for (int kc = 0; kc < 3; kc++) {
        float acc1[2][4][4];
        #pragma unroll
        for (int mt = 0; mt < 2; mt++)
            #pragma unroll
            for (int nt = 0; nt < 4; nt++)
                #pragma unroll
                for (int c = 0; c < 4; c++) acc1[mt][nt][c] = 0.f;
        gemm_pass(AH + aoff, BH + boff, acc1);
        gemm_pass(AH + aoff, BH + BTILE_B + boff, acc1);
        gemm_pass(AL + aoff, BH + boff, acc1);

        // relu + bias + split -> H
        #pragma unroll
        for (int mt = 0; mt < 2; mt++)
            #pragma unroll
            for (int nt = 0; nt < 4; nt++) {
                const int row = mbase + mt*16 + qr;
                const int col = nbase + nt*8 + qc;
                const int cg  = kc*128 + col;
                float v0 = fmaxf(acc1[mt][nt][0] + __ldg(&b1[cg]),   0.f);
                float v1 = fmaxf(acc1[mt][nt][1] + __ldg(&b1[cg+1]), 0.f);
                float v2 = fmaxf(acc1[mt][nt][2] + __ldg(&b1[cg]),   0.f);
                float v3 = fmaxf(acc1[mt][nt][3] + __ldg(&b1[cg+1]), 0.f);
                *reinterpret_cast<uint32_t*>(sHh + row*LDT + col)     = pk2(v0, v1);
                *reinterpret_cast<uint32_t*>(sHl + row*LDT + col)     = pk2(blo(v0), blo(v1));
                *reinterpret_cast<uint32_t*>(sHh + (row+8)*LDT + col) = pk2(v2, v3);
                *reinterpret_cast<uint32_t*>(sHl + (row+8)*LDT + col) = pk2(blo(v2), blo(v3));
            }
        __syncthreads();

        // stage W2(kc)
        {
            const char* src = reinterpret_cast<const char*>(g_wb + (3+kc)*2*TILE_E);
            for (int i = tid; i < 2*BTILE_B/16; i += 512) cpa16(BH + i*16, src + i*16);
            cpa_commit(); cpa_waitg<0>();
        }
        __syncthreads();

        gemm_pass(HH + aoff, BH + boff, acc2);
        gemm_pass(HH + aoff, BH + BTILE_B + boff, acc2);
        gemm_pass(HL + aoff, BH + boff, acc2);

        if (kc < 2) {
            __syncthreads();
            const char* src = reinterpret_cast<const char*>(g_wb + (kc+1)*2*TILE_E);
            for (int i = tid; i < 2*BTILE_B/16; i += 512) cpa16(BH + i*16, src + i*16);
            cpa_commit(); cpa_waitg<0>();
            __syncthreads();
        }
    }
    __syncthreads();

    // dump acc2 + bias + residual into fp32 smem [128][132] (overwrites A region)
    float* sF = reinterpret_cast<float*>(smem);
    #pragma unroll
    for (int mt = 0; mt < 2; mt++)
        #pragma unroll
        for (int nt = 0; nt < 4; nt++) {
            const int row = mbase + mt*16 + qr;
            const int col = nbase + nt*8 + qc;
            const float2 e0 = *reinterpret_cast<const float2*>(&g_emb[(base+row)*128 + col]);
            const float2 e1 = *reinterpret_cast<const float2*>(&g_emb[(base+row+8)*128 + col]);
            const float bb0 = __ldg(&b2[col]), bb1 = __ldg(&b2[col+1]);
            sF[row*132 + col]       = acc2[mt][nt][0] + bb0 + e0.x;
            sF[row*132 + col + 1]   = acc2[mt][nt][1] + bb1 + e0.y;
            sF[(row+8)*132 + col]   = acc2[mt][nt][2] + bb0 + e1.x;
            sF[(row+8)*132 + col+1] = acc2[mt][nt][3] + bb1 + e1.y;
        }
    __syncthreads();

    // LN2 + transposed store: 4 threads per row
    {
        const int row = tid >> 2;
        const int sub = tid & 3;
        float sum = 0.f, sq = 0.f;
        #pragma unroll 8
        for (int c = sub*32; c < sub*32 + 32; c++) {
            float v = sF[row*132 + c];
            sum += v; sq += v*v;
        }
        sum += __shfl_xor_sync(FULLMASK, sum, 1);
        sq  += __shfl_xor_sync(FULLMASK, sq, 1);
        sum += __shfl_xor_sync(FULLMASK, sum, 2);
        sq  += __shfl_xor_sync(FULLMASK, sq, 2);
        const float mu = sum * (1.0f/128.0f);
        const float istd = rsqrtf(sq*(1.0f/128.0f) - mu*mu + 1e-5f);

        const int n = base + row;
        const int s = n % S_;
        const int bm = n / S_;
        float* op = d_out + (((s*B_ + (bm >> 3))*M_ + (bm & 7)) << 7);
        #pragma unroll 4
        for (int c = sub*32; c < sub*32 + 32; c += 4) {
            float4 o4;
            o4.x = (sF[row*132+c+0]-mu)*istd*__ldg(&ln2_g[c+0]) + __ldg(&ln2_b[c+0]);
            o4.y = (sF[row*132+c+1]-mu)*istd*__ldg(&ln2_g[c+1]) + __ldg(&ln2_b[c+1]);
            o4.z = (sF[row*132+c+2]-mu)*istd*__ldg(&ln2_g[c+2]) + __ldg(&ln2_b[c+2]);
            o4.w = (sF[row*132+c+3]-mu)*istd*__ldg(&ln2_g[c+3]) + __ldg(&ln2_b[c+3]);
            *reinterpret_cast<float4*>(op + c) = o4;
        }
    }
}

// ================= launcher =================
extern "C" void kernel_launch(void* const* d_in, const int* in_sizes, int n_in,
                              void* d_out, int out_size)
{
    const float* roads  = (const float*)d_in[0];
    const float* ms     = (const float*)d_in[2];
    const float* lin_w  = (const float*)d_in[3];
    const float* lin_b  = (const float*)d_in[4];
    const float* wq     = (const float*)d_in[5];
    const float* wk     = (const float*)d_in[6];
    const float* wv     = (const float*)d_in[7];
    const float* bq     = (const float*)d_in[8];
    const float* bk     = (const float*)d_in[9];
    const float* bv     = (const float*)d_in[10];
    const float* out_w  = (const float*)d_in[11];
    const float* out_b  = (const float*)d_in[12];
    const float* ln1_g  = (const float*)d_in[13];
    const float* ln1_b  = (const float*)d_in[14];
    const float* w1     = (const float*)d_in[15];
    const float* b1     = (const float*)d_in[16];
    const float* w2     = (const float*)d_in[17];
    const float* b2     = (const float*)d_in[18];
    const float* ln2_g  = (const float*)d_in[19];
    const float* ln2_b  = (const float*)d_in[20];
    float* out = (float*)d_out;

    cudaFuncSetAttribute(k_pre, cudaFuncAttributeMaxDynamicSharedMemorySize, PRE_DSMEM);
    cudaFuncSetAttribute(k_ffn, cudaFuncAttributeMaxDynamicSharedMemorySize, K3_DSMEM);

    k_pre<<<107, 256, PRE_DSMEM>>>(roads, ms, lin_w, lin_b, wq, wk, wv, bq, bk, bv,
                                   out_w, out_b, w1, w2, out);
    k_attn<<<N_SEG/32, 256>>>(roads, ln1_g, ln1_b);
    k_ffn<<<N_SEG/128, 512, K3_DSMEM>>>(b1, b2, ln2_g, ln2_b, out);
}

// round 8
// speedup vs baseline: 1.1078x; 1.1078x over previous
#include <cuda_runtime.h>
#include <cuda_bf16.h>
#include <math.h>
#include <stdint.h>

#define N_SEG 12800
#define D_ 128
#define S_ 100
#define B_ 16
#define M_ 8
#define P_ 40
#define OUT_ELEMS (S_*B_*M_*D_)   // 1638400
#define FULLMASK 0xffffffffu

#define LDT 136                    // padded bf16 row stride
#define TILE_E (128*LDT)           // 128-row tile elems
#define T_BYTES (TILE_E*2)         // 34816

// ---------------- folded weights + scratch ----------------
__device__ float g_score_w[24];     // [a*8+h]
__device__ float g_score_c[8];
__device__ float g_W2[24*128];      // [(h*3+a)*128 + j]
__device__ float g_c2[128];
__device__ float g_emb[N_SEG*D_];   // post-LN1 embeddings (6.5MB scratch)
// pre-split bf16 weight tiles [n][LDT]; pair w: [hi,lo]. w=0..2: w1 n-chunks, 3..5: w2 k-chunks
__device__ __align__(16) __nv_bfloat16 g_wb[6*2*TILE_E];

__device__ __forceinline__ unsigned pk2(float a, float b) {
    __nv_bfloat162 t = __floats2bfloat162_rn(a, b);
    return *reinterpret_cast<unsigned*>(&t);
}
__device__ __forceinline__ float blo(float x) {
    return x - __bfloat162float(__float2bfloat16(x));
}
__device__ __forceinline__ void mma16816(float* c, const uint32_t* a, uint32_t b0, uint32_t b1) {
    asm volatile("mma.sync.aligned.m16n8k16.row.col.f32.bf16.bf16.f32 "
        "{%0,%1,%2,%3}, {%4,%5,%6,%7}, {%8,%9}, {%0,%1,%2,%3};"
        : "+f"(c[0]), "+f"(c[1]), "+f"(c[2]), "+f"(c[3])
        : "r"(a[0]), "r"(a[1]), "r"(a[2]), "r"(a[3]), "r"(b0), "r"(b1));
}
__device__ __forceinline__ void ldsm4(uint32_t* r, uint32_t addr) {
    asm volatile("ldmatrix.sync.aligned.m8n8.x4.shared.b16 {%0,%1,%2,%3}, [%4];"
        : "=r"(r[0]), "=r"(r[1]), "=r"(r[2]), "=r"(r[3]) : "r"(addr));
}
__device__ __forceinline__ void cpa16(uint32_t daddr, const void* g) {
    asm volatile("cp.async.cg.shared.global [%0], [%1], 16;" :: "r"(daddr), "l"(g));
}
__device__ __forceinline__ void cpa_commit() {
    asm volatile("cp.async.commit_group;" ::: "memory");
}
template<int N> __device__ __forceinline__ void cpa_waitg() {
    asm volatile("cp.async.wait_group %0;" :: "n"(N) : "memory");
}

// ================= kernel 1: weight split (6 blocks) + pipelined fold (block 6) =================
#define PRE_DSMEM (192*1024)

__global__ void k_pre(const float* __restrict__ ms,   const float* __restrict__ lin_w,
                      const float* __restrict__ lin_b,const float* __restrict__ wq,
                      const float* __restrict__ wk,   const float* __restrict__ wv,
                      const float* __restrict__ bq,   const float* __restrict__ bk,
                      const float* __restrict__ bv,   const float* __restrict__ out_w,
                      const float* __restrict__ out_b,
                      const float* __restrict__ w1,   const float* __restrict__ w2)
{
    const int t = threadIdx.x;
    if (blockIdx.x < 6) {
        const int w = blockIdx.x;
        __nv_bfloat16* dh = g_wb + (w*2+0)*TILE_E;
        __nv_bfloat16* dl = g_wb + (w*2+1)*TILE_E;
        for (int i = t; i < 128*32; i += 256) {
            int n = i >> 5, k4 = (i & 31) << 2;
            float4 v = (w < 3)
                ? make_float4(w1[(k4+0)*384 + w*128 + n], w1[(k4+1)*384 + w*128 + n],
                              w1[(k4+2)*384 + w*128 + n], w1[(k4+3)*384 + w*128 + n])
                : make_float4(w2[((w-3)*128 + k4+0)*128 + n], w2[((w-3)*128 + k4+1)*128 + n],
                              w2[((w-3)*128 + k4+2)*128 + n], w2[((w-3)*128 + k4+3)*128 + n]);
            __nv_bfloat16 h0 = __float2bfloat16(v.x), h1 = __float2bfloat16(v.y);
            __nv_bfloat16 h2 = __float2bfloat16(v.z), h3 = __float2bfloat16(v.w);
            int off = n*LDT + k4;
            *reinterpret_cast<uint2*>(dh + off) = make_uint2(
                (uint32_t)*(uint16_t*)&h0 | ((uint32_t)*(uint16_t*)&h1 << 16),
                (uint32_t)*(uint16_t*)&h2 | ((uint32_t)*(uint16_t*)&h3 << 16));
            *reinterpret_cast<uint2*>(dl + off) = make_uint2(
                pk2(v.x - __bfloat162float(h0), v.y - __bfloat162float(h1)),
                pk2(v.z - __bfloat162float(h2), v.w - __bfloat162float(h3)));
        }
        return;
    }

    // -------- block 6: fold attention weights (cp.async pipelined) --------
    extern __shared__ float W[];    // 3 x 16384 floats
    float* W0 = W;
    float* W1 = W + 16384;
    float* Wv = W + 32768;
    __shared__ float q[128];
    __shared__ float wkq[128*8];
    __shared__ float lwv[3*128];
    __shared__ float cv[128];
    __shared__ float ms_s[128], lb_s[128];

    const uint32_t wsb = (uint32_t)__cvta_generic_to_shared(W);
    if (t < 128) { ms_s[t] = ms[t]; lb_s[t] = lin_b[t]; }

    for (int i = t; i < 4096; i += 256) cpa16(wsb + i*16, (const char*)wq + i*16);
    cpa_commit();
    for (int i = t; i < 4096; i += 256) cpa16(wsb + 65536 + i*16, (const char*)wk + i*16);
    cpa_commit();
    for (int i = t; i < 4096; i += 256) cpa16(wsb + 131072 + i*16, (const char*)wv + i*16);
    cpa_commit();

    cpa_waitg<2>();
    __syncthreads();
    if (t < 128) {
        float acc = bq[t];
        #pragma unroll 8
        for (int e = 0; e < 128; e++) acc += ms_s[e]*W0[e*128+t];
        q[t] = acc;
    }
    __syncthreads();

    for (int i = t; i < 4096; i += 256) cpa16(wsb + i*16, (const char*)out_w + i*16);
    cpa_commit();

    cpa_waitg<2>();
    __syncthreads();
    if (t < 128) {
        #pragma unroll
        for (int h = 0; h < 8; h++) {
            float s = 0.f;
            #pragma unroll
            for (int j = 0; j < 16; j++) s += W1[t*128 + h*16 + j]*q[h*16 + j];
            wkq[t*8 + h] = s;
        }
    }
    __syncthreads();

    if (t < 24) {
        int a = t/8, h = t%8;
        float s = 0.f;
        #pragma unroll 8
        for (int d = 0; d < 128; d++) s += lin_w[a*128+d]*wkq[d*8+h];
        g_score_w[a*8+h] = 0.25f*s;
    } else if (t < 32) {
        int h = t-24;
        float s = 0.f;
        #pragma unroll 8
        for (int d = 0; d < 128; d++) s += lb_s[d]*wkq[d*8+h];
        #pragma unroll
        for (int j = 0; j < 16; j++) s += q[h*16+j]*bk[h*16+j];
        g_score_c[h] = 0.25f*s;
    }

    cpa_waitg<1>();
    __syncthreads();
    if (t < 128) {
        float s0=0.f, s1=0.f, s2=0.f, sc=0.f;
        #pragma unroll 8
        for (int e = 0; e < 128; e++) {
            float w = Wv[e*128 + t];
            s0 += lin_w[0*128+e]*w;
            s1 += lin_w[1*128+e]*w;
            s2 += lin_w[2*128+e]*w;
            sc += lb_s[e]*w;
        }
        lwv[0*128+t]=s0; lwv[1*128+t]=s1; lwv[2*128+t]=s2;
        cv[t] = sc + bv[t];
    }
    cpa_waitg<0>();
    __syncthreads();
    if (t < 128) {
        #pragma unroll
        for (int h = 0; h < 8; h++)
            #pragma unroll
            for (int a = 0; a < 3; a++) {
                float s = 0.f;
                #pragma unroll
                for (int dd = 0; dd < 16; dd++) {
                    int d = h*16 + dd;
                    s += lwv[a*128+d]*W0[d*128+t];
                }
                g_W2[(h*3+a)*128 + t] = s;
            }
        float s = out_b[t];
        #pragma unroll 8
        for (int d = 0; d < 128; d++) s += cv[d]*W0[d*128+t];
        g_c2[t] = s;
    }
}

// ================= kernel 2: attention pooling + LN1 + raw seg flags =================
__global__ __launch_bounds__(256)
void k_attn(const float* __restrict__ roads,
            const float* __restrict__ ln1_g, const float* __restrict__ ln1_b,
            float* __restrict__ d_out)
{
    __shared__ float sW2[24*128];
    __shared__ float sc2[128], sg[128], sb_[128];
    const int tid = threadIdx.x;
    for (int i = tid; i < 24*128; i += 256) sW2[i] = g_W2[i];
    if (tid < 128) { sc2[tid] = g_c2[tid]; sg[tid] = ln1_g[tid]; sb_[tid] = ln1_b[tid]; }
    __syncthreads();

    const int wid  = tid >> 5;
    const int lane = tid & 31;

    #pragma unroll
    for (int seg = 0; seg < 4; seg++) {
        const int n = (blockIdx.x*8 + wid)*4 + seg;

        const float4* rp = reinterpret_cast<const float4*>(roads) + n*P_;
        float4 a0 = rp[lane];
        float4 a1 = make_float4(0.f,0.f,0.f,0.f);
        if (lane < 8) a1 = rp[32 + lane];

        bool v0 = (a0.w != 0.0f);
        bool v1 = (lane < 8) && (a1.w != 0.0f);
        unsigned bm0 = __ballot_sync(FULLMASK, v0);
        unsigned bm1 = __ballot_sync(FULLMASK, v1);
        const bool seg_empty = ((bm0 | bm1) == 0u);
        if (seg_empty && lane == 0) v0 = true;

        float pa[24];
        #pragma unroll
        for (int h = 0; h < 8; h++) {
            const float sw0 = __ldg(&g_score_w[0*8+h]);
            const float sw1 = __ldg(&g_score_w[1*8+h]);
            const float sw2 = __ldg(&g_score_w[2*8+h]);
            const float sc  = __ldg(&g_score_c[h]);
            float s0 = sc + a0.x*sw0 + a0.y*sw1 + a0.z*sw2;
            float s1 = sc + a1.x*sw0 + a1.y*sw1 + a1.z*sw2;
            float mx = fmaxf(v0 ? s0 : -1e30f, v1 ? s1 : -1e30f);
            #pragma unroll
            for (int o = 16; o; o >>= 1) mx = fmaxf(mx, __shfl_xor_sync(FULLMASK, mx, o));
            float e0 = v0 ? __expf(s0 - mx) : 0.0f;
            float e1 = v1 ? __expf(s1 - mx) : 0.0f;
            float t0 = e0 + e1;
            float t1 = e0*a0.x + e1*a1.x;
            float t2 = e0*a0.y + e1*a1.y;
            float t3 = e0*a0.z + e1*a1.z;
            #pragma unroll
            for (int o = 16; o; o >>= 1) {
                t0 += __shfl_xor_sync(FULLMASK, t0, o);
                t1 += __shfl_xor_sync(FULLMASK, t1, o);
                t2 += __shfl_xor_sync(FULLMASK, t2, o);
                t3 += __shfl_xor_sync(FULLMASK, t3, o);
            }
            float inv = 1.0f / t0;
            pa[h*3+0] = t1*inv;
            pa[h*3+1] = t2*inv;
            pa[h*3+2] = t3*inv;
        }

        float y[4];
        #pragma unroll
        for (int u = 0; u < 4; u++) {
            int j = lane + 32*u;
            float acc = sc2[j];
            #pragma unroll
            for (int i = 0; i < 24; i++) acc += pa[i]*sW2[i*128 + j];
            y[u] = acc;
        }

        float loc = y[0]+y[1]+y[2]+y[3];
        #pragma unroll
        for (int o = 16; o; o >>= 1) loc += __shfl_xor_sync(FULLMASK, loc, o);
        const float mu = loc * (1.0f/128.0f);
        float sq = 0.f;
        #pragma unroll
        for (int u = 0; u < 4; u++) { float d = y[u]-mu; sq += d*d; }
        #pragma unroll
        for (int o = 16; o; o >>= 1) sq += __shfl_xor_sync(FULLMASK, sq, o);
        const float istd = rsqrtf(sq*(1.0f/128.0f) + 1e-5f);
        #pragma unroll
        for (int u = 0; u < 4; u++) {
            int j = lane + 32*u;
            g_emb[n*128 + j] = (y[u]-mu)*istd*sg[j] + sb_[j];
        }
        if (lane == 0) d_out[OUT_ELEMS + n] = seg_empty ? 1.0f : 0.0f;
    }
}

// ================= kernel 3: HMMA FFN (R5 winner: 256 thr, warp m32 x n64) =================
#define K3_DSMEM (6*T_BYTES)    // 208896

__device__ __forceinline__ void gemm_pass(uint32_t aB, uint32_t bB, float (&acc)[2][8][4])
{
    #pragma unroll
    for (int k = 0; k < 8; k++) {
        uint32_t a0[4], a1[4];
        ldsm4(a0, aB + k*32);
        ldsm4(a1, aB + 16*LDT*2 + k*32);
        #pragma unroll
        for (int ntp = 0; ntp < 4; ntp++) {
            uint32_t b[4];
            ldsm4(b, bB + ntp*16*LDT*2 + k*32);
            mma16816(acc[0][2*ntp+0], a0, b[0], b[1]);
            mma16816(acc[1][2*ntp+0], a1, b[0], b[1]);
            mma16816(acc[0][2*ntp+1], a0, b[2], b[3]);
            mma16816(acc[1][2*ntp+1], a1, b[2], b[3]);
        }
    }
}

__global__ __launch_bounds__(256, 1)
void k_ffn(const float* __restrict__ b1, const float* __restrict__ b2,
           const float* __restrict__ ln2_g, const float* __restrict__ ln2_b,
           float* __restrict__ d_out)
{
    extern __shared__ __align__(16) char smem[];
    __nv_bfloat16* sAh = reinterpret_cast<__nv_bfloat16*>(smem);
    __nv_bfloat16* sAl = sAh + TILE_E;
    __nv_bfloat16* sHh = sAl + TILE_E;
    __nv_bfloat16* sHl = sHh + TILE_E;

    const uint32_t sb = (uint32_t)__cvta_generic_to_shared(smem);
    const uint32_t AH = sb, AL = AH + T_BYTES, HH = AL + T_BYTES,
                   HL = HH + T_BYTES, BH = HL + T_BYTES;

    const int tid  = threadIdx.x;
    const int wid  = tid >> 5;
    const int lane = tid & 31;
    const int qr   = lane >> 2;
    const int qc   = (lane & 3) << 1;
    const int mbase = (wid >> 1) * 32;
    const int nbase = (wid & 1) * 64;
    const int base  = blockIdx.x * 128;

    const uint32_t aoff = (uint32_t)(((lane & 15)*LDT + (lane >> 4)*8)*2 + mbase*LDT*2);
    const uint32_t boff = (uint32_t)((((lane & 7) + ((lane >> 4) << 3))*LDT
                                      + ((lane >> 3) & 1)*8)*2 + nbase*LDT*2);

    // stage W1(0)
    {
        const char* src = reinterpret_cast<const char*>(g_wb);
        for (int i = tid; i < 2*T_BYTES/16; i += 256) cpa16(BH + i*16, src + i*16);
        cpa_commit();
    }

    // block 0: seg_mask all_seg fix (flags written by k_attn)
    if (blockIdx.x == 0 && tid < 128) {
        float allm = 1.0f;
        #pragma unroll 4
        for (int s = 0; s < S_; s++)
            allm = fminf(allm, d_out[OUT_ELEMS + tid*S_ + s]);
        if (allm > 0.5f) d_out[OUT_ELEMS + tid*S_] = 0.0f;
    }

    // stage A = emb tile (bf16 hi/lo)
    {
        const float4* eb = reinterpret_cast<const float4*>(g_emb + base*128);
        for (int i = tid; i < 4096; i += 256) {
            int r = i >> 5, c4 = (i & 31) << 2;
            float4 v = eb[i];
            int off = r*LDT + c4;
            *reinterpret_cast<uint2*>(sAh + off) = make_uint2(pk2(v.x,v.y), pk2(v.z,v.w));
            *reinterpret_cast<uint2*>(sAl + off) =
                make_uint2(pk2(blo(v.x),blo(v.y)), pk2(blo(v.z),blo(v.w)));
        }
    }
    cpa_waitg<0>();
    __syncthreads();

    float acc2[2][8][4];
    #pragma unroll
    for (int mt = 0; mt < 2; mt++)
        #pragma unroll
        for (int nt = 0; nt < 8; nt++)
            #pragma unroll
            for (int c = 0; c < 4; c++) acc2[mt][nt][c] = 0.f;

    for (int kc = 0; kc < 3; kc++) {
        float acc1[2][8][4];
        #pragma unroll
        for (int mt = 0; mt < 2; mt++)
            #pragma unroll
            for (int nt = 0; nt < 8; nt++)
                #pragma unroll
                for (int c = 0; c < 4; c++) acc1[mt][nt][c] = 0.f;
        gemm_pass(AH + aoff, BH + boff, acc1);
        gemm_pass(AH + aoff, BH + T_BYTES + boff, acc1);
        gemm_pass(AL + aoff, BH + boff, acc1);

        // relu + bias + split -> H
        #pragma unroll
        for (int mt = 0; mt < 2; mt++)
            #pragma unroll
            for (int nt = 0; nt < 8; nt++) {
                const int row = mbase + mt*16 + qr;
                const int col = nbase + nt*8 + qc;
                const int cg  = kc*128 + col;
                float v0 = fmaxf(acc1[mt][nt][0] + __ldg(&b1[cg]),   0.f);
                float v1 = fmaxf(acc1[mt][nt][1] + __ldg(&b1[cg+1]), 0.f);
                float v2 = fmaxf(acc1[mt][nt][2] + __ldg(&b1[cg]),   0.f);
                float v3 = fmaxf(acc1[mt][nt][3] + __ldg(&b1[cg+1]), 0.f);
                *reinterpret_cast<uint32_t*>(sHh + row*LDT + col)     = pk2(v0, v1);
                *reinterpret_cast<uint32_t*>(sHl + row*LDT + col)     = pk2(blo(v0), blo(v1));
                *reinterpret_cast<uint32_t*>(sHh + (row+8)*LDT + col) = pk2(v2, v3);
                *reinterpret_cast<uint32_t*>(sHl + (row+8)*LDT + col) = pk2(blo(v2), blo(v3));
            }
        __syncthreads();

        // stage W2(kc)
        {
            const char* src = reinterpret_cast<const char*>(g_wb + (3+kc)*2*TILE_E);
            for (int i = tid; i < 2*T_BYTES/16; i += 256) cpa16(BH + i*16, src + i*16);
            cpa_commit(); cpa_waitg<0>();
        }
        __syncthreads();

        gemm_pass(HH + aoff, BH + boff, acc2);
        gemm_pass(HH + aoff, BH + T_BYTES + boff, acc2);
        gemm_pass(HL + aoff, BH + boff, acc2);

        if (kc < 2) {
            __syncthreads();
            const char* src = reinterpret_cast<const char*>(g_wb + (kc+1)*2*TILE_E);
            for (int i = tid; i < 2*T_BYTES/16; i += 256) cpa16(BH + i*16, src + i*16);
            cpa_commit(); cpa_waitg<0>();
            __syncthreads();
        }
    }
    __syncthreads();

    // dump acc2 + bias + residual into fp32 smem [128][132]
    float* sF = reinterpret_cast<float*>(smem);
    #pragma unroll
    for (int mt = 0; mt < 2; mt++)
        #pragma unroll
        for (int nt = 0; nt < 8; nt++) {
            const int row = mbase + mt*16 + qr;
            const int col = nbase + nt*8 + qc;
            const float2 e0 = *reinterpret_cast<const float2*>(&g_emb[(base+row)*128 + col]);
            const float2 e1 = *reinterpret_cast<const float2*>(&g_emb[(base+row+8)*128 + col]);
            const float bb0 = __ldg(&b2[col]), bb1 = __ldg(&b2[col+1]);
            sF[row*132 + col]       = acc2[mt][nt][0] + bb0 + e0.x;
            sF[row*132 + col + 1]   = acc2[mt][nt][1] + bb1 + e0.y;
            sF[(row+8)*132 + col]   = acc2[mt][nt][2] + bb0 + e1.x;
            sF[(row+8)*132 + col+1] = acc2[mt][nt][3] + bb1 + e1.y;
        }
    __syncthreads();

    // LN2 + transposed store (2 threads per row)
    {
        const int row = tid >> 1;
        const int sub = tid & 1;
        float sum = 0.f, sq = 0.f;
        #pragma unroll 8
        for (int c = sub*64; c < sub*64 + 64; c++) {
            float v = sF[row*132 + c];
            sum += v; sq += v*v;
        }
        sum += __shfl_xor_sync(FULLMASK, sum, 1);
        sq  += __shfl_xor_sync(FULLMASK, sq, 1);
        const float mu = sum * (1.0f/128.0f);
        const float istd = rsqrtf(sq*(1.0f/128.0f) - mu*mu + 1e-5f);

        const int n = base + row;
        const int s = n % S_;
        const int bm = n / S_;
        float* op = d_out + (((s*B_ + (bm >> 3))*M_ + (bm & 7)) << 7);
        #pragma unroll 4
        for (int c = sub*64; c < sub*64 + 64; c += 4) {
            float4 o4;
            o4.x = (sF[row*132+c+0]-mu)*istd*__ldg(&ln2_g[c+0]) + __ldg(&ln2_b[c+0]);
            o4.y = (sF[row*132+c+1]-mu)*istd*__ldg(&ln2_g[c+1]) + __ldg(&ln2_b[c+1]);
            o4.z = (sF[row*132+c+2]-mu)*istd*__ldg(&ln2_g[c+2]) + __ldg(&ln2_b[c+2]);
            o4.w = (sF[row*132+c+3]-mu)*istd*__ldg(&ln2_g[c+3]) + __ldg(&ln2_b[c+3]);
            *reinterpret_cast<float4*>(op + c) = o4;
        }
    }
}

// ================= launcher =================
extern "C" void kernel_launch(void* const* d_in, const int* in_sizes, int n_in,
                              void* d_out, int out_size)
{
    const float* roads  = (const float*)d_in[0];
    const float* ms     = (const float*)d_in[2];
    const float* lin_w  = (const float*)d_in[3];
    const float* lin_b  = (const float*)d_in[4];
    const float* wq     = (const float*)d_in[5];
    const float* wk     = (const float*)d_in[6];
    const float* wv     = (const float*)d_in[7];
    const float* bq     = (const float*)d_in[8];
    const float* bk     = (const float*)d_in[9];
    const float* bv     = (const float*)d_in[10];
    const float* out_w  = (const float*)d_in[11];
    const float* out_b  = (const float*)d_in[12];
    const float* ln1_g  = (const float*)d_in[13];
    const float* ln1_b  = (const float*)d_in[14];
    const float* w1     = (const float*)d_in[15];
    const float* b1     = (const float*)d_in[16];
    const float* w2     = (const float*)d_in[17];
    const float* b2     = (const float*)d_in[18];
    const float* ln2_g  = (const float*)d_in[19];
    const float* ln2_b  = (const float*)d_in[20];
    float* out = (float*)d_out;

    cudaFuncSetAttribute(k_pre, cudaFuncAttributeMaxDynamicSharedMemorySize, PRE_DSMEM);
    cudaFuncSetAttribute(k_ffn, cudaFuncAttributeMaxDynamicSharedMemorySize, K3_DSMEM);

    k_pre<<<7, 256, PRE_DSMEM>>>(ms, lin_w, lin_b, wq, wk, wv, bq, bk, bv,
                                 out_w, out_b, w1, w2);
    k_attn<<<N_SEG/32, 256>>>(roads, ln1_g, ln1_b, out);
    k_ffn<<<N_SEG/128, 256, K3_DSMEM>>>(b1, b2, ln2_g, ln2_b, out);
}

// round 12
// speedup vs baseline: 1.1586x; 1.0458x over previous
#include <cuda_runtime.h>
#include <cuda_bf16.h>
#include <math.h>
#include <stdint.h>

#define N_SEG 12800
#define D_ 128
#define S_ 100
#define B_ 16
#define M_ 8
#define P_ 40
#define OUT_ELEMS (S_*B_*M_*D_)   // 1638400
#define FULLMASK 0xffffffffu

#define LDT 136                    // padded bf16 row stride
#define TILE_E (128*LDT)           // 128-row tile elems
#define T_BYTES (TILE_E*2)         // 34816

// ---------------- folded weights + scratch ----------------
__device__ float g_score_w[24];     // [a*8+h]
__device__ float g_score_c[8];
__device__ float g_W2[24*128];      // [(h*3+a)*128 + j]
__device__ float g_c2[128];
__device__ float g_emb[N_SEG*D_];   // post-LN1 embeddings (6.5MB scratch)
// pre-split bf16 weight tiles [n][LDT]; pair w: [hi,lo]. w=0..2: w1 n-chunks, 3..5: w2 k-chunks
__device__ __align__(16) __nv_bfloat16 g_wb[6*2*TILE_E];

__device__ __forceinline__ unsigned pk2(float a, float b) {
    __nv_bfloat162 t = __floats2bfloat162_rn(a, b);
    return *reinterpret_cast<unsigned*>(&t);
}
__device__ __forceinline__ float blo(float x) {
    return x - __bfloat162float(__float2bfloat16(x));
}
__device__ __forceinline__ void mma16816(float* c, const uint32_t* a, uint32_t b0, uint32_t b1) {
    asm volatile("mma.sync.aligned.m16n8k16.row.col.f32.bf16.bf16.f32 "
        "{%0,%1,%2,%3}, {%4,%5,%6,%7}, {%8,%9}, {%0,%1,%2,%3};"
        : "+f"(c[0]), "+f"(c[1]), "+f"(c[2]), "+f"(c[3])
        : "r"(a[0]), "r"(a[1]), "r"(a[2]), "r"(a[3]), "r"(b0), "r"(b1));
}
__device__ __forceinline__ void ldsm4(uint32_t* r, uint32_t addr) {
    asm volatile("ldmatrix.sync.aligned.m8n8.x4.shared.b16 {%0,%1,%2,%3}, [%4];"
        : "=r"(r[0]), "=r"(r[1]), "=r"(r[2]), "=r"(r[3]) : "r"(addr));
}
__device__ __forceinline__ void cpa16(uint32_t daddr, const void* g) {
    asm volatile("cp.async.cg.shared.global [%0], [%1], 16;" :: "r"(daddr), "l"(g));
}
__device__ __forceinline__ void cpa_commit() {
    asm volatile("cp.async.commit_group;" ::: "memory");
}
template<int N> __device__ __forceinline__ void cpa_waitg() {
    asm volatile("cp.async.wait_group %0;" :: "n"(N) : "memory");
}

// ================= kernel 1: weight split (6 blocks, smem-staged) + fold (block 6) =================
#define PRE_DSMEM (192*1024)

__global__ void k_pre(const float* __restrict__ ms,   const float* __restrict__ lin_w,
                      const float* __restrict__ lin_b,const float* __restrict__ wq,
                      const float* __restrict__ wk,   const float* __restrict__ wv,
                      const float* __restrict__ bq,   const float* __restrict__ bk,
                      const float* __restrict__ bv,   const float* __restrict__ out_w,
                      const float* __restrict__ out_b,
                      const float* __restrict__ w1,   const float* __restrict__ w2)
{
    const int t = threadIdx.x;
    if (blockIdx.x < 6) {
        // -------- split: stage fp32 chunk [k][n] coalesced, emit [n][k] bf16 hi/lo --------
        extern __shared__ float Wst[];          // 128x128 fp32
        const int w = blockIdx.x;
        const uint32_t wsb = (uint32_t)__cvta_generic_to_shared(Wst);
        // coalesced reads: row k of the chunk (n contiguous)
        for (int i = t; i < 128*32; i += 256) {
            int k = i >> 5, n4 = (i & 31) << 2;
            const float* src = (w < 3) ? &w1[k*384 + w*128 + n4]
                                       : &w2[((w-3)*128 + k)*128 + n4];
            cpa16(wsb + (k*128 + n4)*4, src);
        }
        cpa_commit(); cpa_waitg<0>();
        __syncthreads();

        __nv_bfloat16* dh = g_wb + (w*2+0)*TILE_E;
        __nv_bfloat16* dl = g_wb + (w*2+1)*TILE_E;
        const int n  = t >> 1;
        const int kb = (t & 1) * 64;
        uint4* dh4 = reinterpret_cast<uint4*>(dh + n*LDT + kb);
        uint4* dl4 = reinterpret_cast<uint4*>(dl + n*LDT + kb);
        // 64 k-values per thread: 8 uint4 stores x 8 k each
        #pragma unroll
        for (int g = 0; g < 8; g++) {
            uint32_t h4[4], l4[4];
            #pragma unroll
            for (int j = 0; j < 4; j++) {
                const int k = kb + g*8 + j*2;
                float f0 = Wst[(k+0)*128 + n];
                float f1 = Wst[(k+1)*128 + n];
                __nv_bfloat16 h0 = __float2bfloat16(f0), h1 = __float2bfloat16(f1);
                h4[j] = (uint32_t)*(uint16_t*)&h0 | ((uint32_t)*(uint16_t*)&h1 << 16);
                l4[j] = pk2(f0 - __bfloat162float(h0), f1 - __bfloat162float(h1));
            }
            dh4[g] = make_uint4(h4[0], h4[1], h4[2], h4[3]);
            dl4[g] = make_uint4(l4[0], l4[1], l4[2], l4[3]);
        }
        return;
    }

    // -------- block 6: fold attention weights (cp.async pipelined) --------
    extern __shared__ float W[];    // 3 x 16384 floats
    float* W0 = W;
    float* W1 = W + 16384;
    float* Wv = W + 32768;
    __shared__ float q[128];
    __shared__ float wkq[128*8];
    __shared__ float lwv[3*128];
    __shared__ float cv[128];
    __shared__ float ms_s[128], lb_s[128];

    const uint32_t wsb = (uint32_t)__cvta_generic_to_shared(W);
    if (t < 128) { ms_s[t] = ms[t]; lb_s[t] = lin_b[t]; }

    for (int i = t; i < 4096; i += 256) cpa16(wsb + i*16, (const char*)wq + i*16);
    cpa_commit();
    for (int i = t; i < 4096; i += 256) cpa16(wsb + 65536 + i*16, (const char*)wk + i*16);
    cpa_commit();
    for (int i = t; i < 4096; i += 256) cpa16(wsb + 131072 + i*16, (const char*)wv + i*16);
    cpa_commit();

    cpa_waitg<2>();
    __syncthreads();
    if (t < 128) {
        float acc = bq[t];
        #pragma unroll 8
        for (int e = 0; e < 128; e++) acc += ms_s[e]*W0[e*128+t];
        q[t] = acc;
    }
    __syncthreads();

    for (int i = t; i < 4096; i += 256) cpa16(wsb + i*16, (const char*)out_w + i*16);
    cpa_commit();

    cpa_waitg<2>();
    __syncthreads();
    if (t < 128) {
        #pragma unroll
        for (int h = 0; h < 8; h++) {
            float s = 0.f;
            #pragma unroll
            for (int j = 0; j < 16; j++) s += W1[t*128 + h*16 + j]*q[h*16 + j];
            wkq[t*8 + h] = s;
        }
    }
    __syncthreads();

    if (t < 24) {
        int a = t/8, h = t%8;
        float s = 0.f;
        #pragma unroll 8
        for (int d = 0; d < 128; d++) s += lin_w[a*128+d]*wkq[d*8+h];
        g_score_w[a*8+h] = 0.25f*s;
    } else if (t < 32) {
        int h = t-24;
        float s = 0.f;
        #pragma unroll 8
        for (int d = 0; d < 128; d++) s += lb_s[d]*wkq[d*8+h];
        #pragma unroll
        for (int j = 0; j < 16; j++) s += q[h*16+j]*bk[h*16+j];
        g_score_c[h] = 0.25f*s;
    }

    cpa_waitg<1>();
    __syncthreads();
    if (t < 128) {
        float s0=0.f, s1=0.f, s2=0.f, sc=0.f;
        #pragma unroll 8
        for (int e = 0; e < 128; e++) {
            float w = Wv[e*128 + t];
            s0 += lin_w[0*128+e]*w;
            s1 += lin_w[1*128+e]*w;
            s2 += lin_w[2*128+e]*w;
            sc += lb_s[e]*w;
        }
        lwv[0*128+t]=s0; lwv[1*128+t]=s1; lwv[2*128+t]=s2;
        cv[t] = sc + bv[t];
    }
    cpa_waitg<0>();
    __syncthreads();
    if (t < 128) {
        #pragma unroll
        for (int h = 0; h < 8; h++)
            #pragma unroll
            for (int a = 0; a < 3; a++) {
                float s = 0.f;
                #pragma unroll
                for (int dd = 0; dd < 16; dd++) {
                    int d = h*16 + dd;
                    s += lwv[a*128+d]*W0[d*128+t];
                }
                g_W2[(h*3+a)*128 + t] = s;
            }
        float s = out_b[t];
        #pragma unroll 8
        for (int d = 0; d < 128; d++) s += cv[d]*W0[d*128+t];
        g_c2[t] = s;
    }
}

// ================= kernel 2: attention pooling + LN1 (1 seg/warp) =================
__global__ void k_attn(const float* __restrict__ roads,
                       const float* __restrict__ ln1_g, const float* __restrict__ ln1_b,
                       float* __restrict__ d_out)
{
    const int n    = (blockIdx.x*blockDim.x + threadIdx.x) >> 5;
    const int lane = threadIdx.x & 31;
    if (n >= N_SEG) return;

    const float4* rp = reinterpret_cast<const float4*>(roads) + n*P_;
    float4 a0 = rp[lane];
    float4 a1 = make_float4(0.f,0.f,0.f,0.f);
    if (lane < 8) a1 = rp[32 + lane];

    bool v0 = (a0.w != 0.0f);
    bool v1 = (lane < 8) && (a1.w != 0.0f);
    unsigned bm0 = __ballot_sync(FULLMASK, v0);
    unsigned bm1 = __ballot_sync(FULLMASK, v1);
    const bool seg_empty = ((bm0 | bm1) == 0u);
    if (seg_empty && lane == 0) v0 = true;

    float pa[24];
    #pragma unroll
    for (int h = 0; h < 8; h++) {
        const float sw0 = __ldg(&g_score_w[0*8+h]);
        const float sw1 = __ldg(&g_score_w[1*8+h]);
        const float sw2 = __ldg(&g_score_w[2*8+h]);
        const float sc  = __ldg(&g_score_c[h]);
        float s0 = sc + a0.x*sw0 + a0.y*sw1 + a0.z*sw2;
        float s1 = sc + a1.x*sw0 + a1.y*sw1 + a1.z*sw2;
        float mx = fmaxf(v0 ? s0 : -1e30f, v1 ? s1 : -1e30f);
        #pragma unroll
        for (int o = 16; o; o >>= 1) mx = fmaxf(mx, __shfl_xor_sync(FULLMASK, mx, o));
        float e0 = v0 ? __expf(s0 - mx) : 0.0f;
        float e1 = v1 ? __expf(s1 - mx) : 0.0f;
        float t0 = e0 + e1;
        float t1 = e0*a0.x + e1*a1.x;
        float t2 = e0*a0.y + e1*a1.y;
        float t3 = e0*a0.z + e1*a1.z;
        #pragma unroll
        for (int o = 16; o; o >>= 1) {
            t0 += __shfl_xor_sync(FULLMASK, t0, o);
            t1 += __shfl_xor_sync(FULLMASK, t1, o);
            t2 += __shfl_xor_sync(FULLMASK, t2, o);
            t3 += __shfl_xor_sync(FULLMASK, t3, o);
        }
        float inv = 1.0f / t0;
        pa[h*3+0] = t1*inv;
        pa[h*3+1] = t2*inv;
        pa[h*3+2] = t3*inv;
    }

    float y[4];
    #pragma unroll
    for (int u = 0; u < 4; u++) {
        int j = lane + 32*u;
        float acc = __ldg(&g_c2[j]);
        #pragma unroll
        for (int i = 0; i < 24; i++) acc += pa[i]*__ldg(&g_W2[i*128 + j]);
        y[u] = acc;
    }

    float loc = y[0]+y[1]+y[2]+y[3];
    #pragma unroll
    for (int o = 16; o; o >>= 1) loc += __shfl_xor_sync(FULLMASK, loc, o);
    const float mu = loc * (1.0f/128.0f);
    float sq = 0.f;
    #pragma unroll
    for (int u = 0; u < 4; u++) { float d = y[u]-mu; sq += d*d; }
    #pragma unroll
    for (int o = 16; o; o >>= 1) sq += __shfl_xor_sync(FULLMASK, sq, o);
    const float istd = rsqrtf(sq*(1.0f/128.0f) + 1e-5f);
    #pragma unroll
    for (int u = 0; u < 4; u++) {
        int j = lane + 32*u;
        g_emb[n*128 + j] = (y[u]-mu)*istd*__ldg(&ln1_g[j]) + __ldg(&ln1_b[j]);
    }

    if (lane == 0) d_out[OUT_ELEMS + n] = seg_empty ? 1.0f : 0.0f;
}

// ================= kernel 3: HMMA FFN (256 thr, warp m32 x n64) =================
#define K3_DSMEM (6*T_BYTES)    // 208896

__device__ __forceinline__ void gemm_pass(uint32_t aB, uint32_t bB, float (&acc)[2][8][4])
{
    #pragma unroll
    for (int k = 0; k < 8; k++) {
        uint32_t a0[4], a1[4];
        ldsm4(a0, aB + k*32);
        ldsm4(a1, aB + 16*LDT*2 + k*32);
        #pragma unroll
        for (int ntp = 0; ntp < 4; ntp++) {
            uint32_t b[4];
            ldsm4(b, bB + ntp*16*LDT*2 + k*32);
            mma16816(acc[0][2*ntp+0], a0, b[0], b[1]);
            mma16816(acc[1][2*ntp+0], a1, b[0], b[1]);
            mma16816(acc[0][2*ntp+1], a0, b[2], b[3]);
            mma16816(acc[1][2*ntp+1], a1, b[2], b[3]);
        }
    }
}

__global__ __launch_bounds__(256, 1)
void k_ffn(const float* __restrict__ b1, const float* __restrict__ b2,
           const float* __restrict__ ln2_g, const float* __restrict__ ln2_b,
           float* __restrict__ d_out)
{
    extern __shared__ __align__(16) char smem[];
    __nv_bfloat16* sAh = reinterpret_cast<__nv_bfloat16*>(smem);
    __nv_bfloat16* sAl = sAh + TILE_E;
    __nv_bfloat16* sHh = sAl + TILE_E;
    __nv_bfloat16* sHl = sHh + TILE_E;

    const uint32_t sb = (uint32_t)__cvta_generic_to_shared(smem);
    const uint32_t AH = sb, AL = AH + T_BYTES, HH = AL + T_BYTES,
                   HL = HH + T_BYTES, BH = HL + T_BYTES;

    const int tid  = threadIdx.x;
    const int wid  = tid >> 5;
    const int lane = tid & 31;
    const int qr   = lane >> 2;
    const int qc   = (lane & 3) << 1;
    const int mbase = (wid >> 1) * 32;
    const int nbase = (wid & 1) * 64;
    const int base  = blockIdx.x * 128;

    const uint32_t aoff = (uint32_t)(((lane & 15)*LDT + (lane >> 4)*8)*2 + mbase*LDT*2);
    const uint32_t boff = (uint32_t)((((lane & 7) + ((lane >> 4) << 3))*LDT
                                      + ((lane >> 3) & 1)*8)*2 + nbase*LDT*2);

    // stage W1(0)
    {
        const char* src = reinterpret_cast<const char*>(g_wb);
        for (int i = tid; i < 2*T_BYTES/16; i += 256) cpa16(BH + i*16, src + i*16);
        cpa_commit();
    }

    // block 0: seg_mask all_seg fix (flags written by k_attn)
    if (blockIdx.x == 0 && tid < 128) {
        float allm = 1.0f;
        #pragma unroll 4
        for (int s = 0; s < S_; s++)
            allm = fminf(allm, d_out[OUT_ELEMS + tid*S_ + s]);
        if (allm > 0.5f) d_out[OUT_ELEMS + tid*S_] = 0.0f;
    }

    // stage A = emb tile (bf16 hi/lo)
    {
        const float4* eb = reinterpret_cast<const float4*>(g_emb + base*128);
        for (int i = tid; i < 4096; i += 256) {
            int r = i >> 5, c4 = (i & 31) << 2;
            float4 v = eb[i];
            int off = r*LDT + c4;
            *reinterpret_cast<uint2*>(sAh + off) = make_uint2(pk2(v.x,v.y), pk2(v.z,v.w));
            *reinterpret_cast<uint2*>(sAl + off) =
                make_uint2(pk2(blo(v.x),blo(v.y)), pk2(blo(v.z),blo(v.w)));
        }
    }
    cpa_waitg<0>();
    __syncthreads();

    float acc2[2][8][4];
    #pragma unroll
    for (int mt = 0; mt < 2; mt++)
        #pragma unroll
        for (int nt = 0; nt < 8; nt++)
            #pragma unroll
            for (int c = 0; c < 4; c++) acc2[mt][nt][c] = 0.f;

    for (int kc = 0; kc < 3; kc++) {
        float acc1[2][8][4];
        #pragma unroll
        for (int mt = 0; mt < 2; mt++)
            #pragma unroll
            for (int nt = 0; nt < 8; nt++)
                #pragma unroll
                for (int c = 0; c < 4; c++) acc1[mt][nt][c] = 0.f;
        gemm_pass(AH + aoff, BH + boff, acc1);
        gemm_pass(AH + aoff, BH + T_BYTES + boff, acc1);
        gemm_pass(AL + aoff, BH + boff, acc1);

        // relu + bias + split -> H
        #pragma unroll
        for (int mt = 0; mt < 2; mt++)
            #pragma unroll
            for (int nt = 0; nt < 8; nt++) {
                const int row = mbase + mt*16 + qr;
                const int col = nbase + nt*8 + qc;
                const int cg  = kc*128 + col;
                float v0 = fmaxf(acc1[mt][nt][0] + __ldg(&b1[cg]),   0.f);
                float v1 = fmaxf(acc1[mt][nt][1] + __ldg(&b1[cg+1]), 0.f);
                float v2 = fmaxf(acc1[mt][nt][2] + __ldg(&b1[cg]),   0.f);
                float v3 = fmaxf(acc1[mt][nt][3] + __ldg(&b1[cg+1]), 0.f);
                *reinterpret_cast<uint32_t*>(sHh + row*LDT + col)     = pk2(v0, v1);
                *reinterpret_cast<uint32_t*>(sHl + row*LDT + col)     = pk2(blo(v0), blo(v1));
                *reinterpret_cast<uint32_t*>(sHh + (row+8)*LDT + col) = pk2(v2, v3);
                *reinterpret_cast<uint32_t*>(sHl + (row+8)*LDT + col) = pk2(blo(v2), blo(v3));
            }
        __syncthreads();

        // stage W2(kc)
        {
            const char* src = reinterpret_cast<const char*>(g_wb + (3+kc)*2*TILE_E);
            for (int i = tid; i < 2*T_BYTES/16; i += 256) cpa16(BH + i*16, src + i*16);
            cpa_commit(); cpa_waitg<0>();
        }
        __syncthreads();

        gemm_pass(HH + aoff, BH + boff, acc2);
        gemm_pass(HH + aoff, BH + T_BYTES + boff, acc2);
        gemm_pass(HL + aoff, BH + boff, acc2);

        if (kc < 2) {
            __syncthreads();
            const char* src = reinterpret_cast<const char*>(g_wb + (kc+1)*2*TILE_E);
            for (int i = tid; i < 2*T_BYTES/16; i += 256) cpa16(BH + i*16, src + i*16);
            cpa_commit(); cpa_waitg<0>();
            __syncthreads();
        }
    }
    __syncthreads();

    // dump acc2 + bias + residual into fp32 smem [128][132]
    float* sF = reinterpret_cast<float*>(smem);
    #pragma unroll
    for (int mt = 0; mt < 2; mt++)
        #pragma unroll
        for (int nt = 0; nt < 8; nt++) {
            const int row = mbase + mt*16 + qr;
            const int col = nbase + nt*8 + qc;
            const float2 e0 = *reinterpret_cast<const float2*>(&g_emb[(base+row)*128 + col]);
            const float2 e1 = *reinterpret_cast<const float2*>(&g_emb[(base+row+8)*128 + col]);
            const float bb0 = __ldg(&b2[col]), bb1 = __ldg(&b2[col+1]);
            sF[row*132 + col]       = acc2[mt][nt][0] + bb0 + e0.x;
            sF[row*132 + col + 1]   = acc2[mt][nt][1] + bb1 + e0.y;
            sF[(row+8)*132 + col]   = acc2[mt][nt][2] + bb0 + e1.x;
            sF[(row+8)*132 + col+1] = acc2[mt][nt][3] + bb1 + e1.y;
        }
    __syncthreads();

    // LN2 + transposed store (2 threads per row)
    {
        const int row = tid >> 1;
        const int sub = tid & 1;
        float sum = 0.f, sq = 0.f;
        #pragma unroll 8
        for (int c = sub*64; c < sub*64 + 64; c++) {
            float v = sF[row*132 + c];
            sum += v; sq += v*v;
        }
        sum += __shfl_xor_sync(FULLMASK, sum, 1);
        sq  += __shfl_xor_sync(FULLMASK, sq, 1);
        const float mu = sum * (1.0f/128.0f);
        const float istd = rsqrtf(sq*(1.0f/128.0f) - mu*mu + 1e-5f);

        const int n = base + row;
        const int s = n % S_;
        const int bm = n / S_;
        float* op = d_out + (((s*B_ + (bm >> 3))*M_ + (bm & 7)) << 7);
        #pragma unroll 4
        for (int c = sub*64; c < sub*64 + 64; c += 4) {
            float4 o4;
            o4.x = (sF[row*132+c+0]-mu)*istd*__ldg(&ln2_g[c+0]) + __ldg(&ln2_b[c+0]);
            o4.y = (sF[row*132+c+1]-mu)*istd*__ldg(&ln2_g[c+1]) + __ldg(&ln2_b[c+1]);
            o4.z = (sF[row*132+c+2]-mu)*istd*__ldg(&ln2_g[c+2]) + __ldg(&ln2_b[c+2]);
            o4.w = (sF[row*132+c+3]-mu)*istd*__ldg(&ln2_g[c+3]) + __ldg(&ln2_b[c+3]);
            *reinterpret_cast<float4*>(op + c) = o4;
        }
    }
}

// ================= launcher =================
extern "C" void kernel_launch(void* const* d_in, const int* in_sizes, int n_in,
                              void* d_out, int out_size)
{
    const float* roads  = (const float*)d_in[0];
    const float* ms     = (const float*)d_in[2];
    const float* lin_w  = (const float*)d_in[3];
    const float* lin_b  = (const float*)d_in[4];
    const float* wq     = (const float*)d_in[5];
    const float* wk     = (const float*)d_in[6];
    const float* wv     = (const float*)d_in[7];
    const float* bq     = (const float*)d_in[8];
    const float* bk     = (const float*)d_in[9];
    const float* bv     = (const float*)d_in[10];
    const float* out_w  = (const float*)d_in[11];
    const float* out_b  = (const float*)d_in[12];
    const float* ln1_g  = (const float*)d_in[13];
    const float* ln1_b  = (const float*)d_in[14];
    const float* w1     = (const float*)d_in[15];
    const float* b1     = (const float*)d_in[16];
    const float* w2     = (const float*)d_in[17];
    const float* b2     = (const float*)d_in[18];
    const float* ln2_g  = (const float*)d_in[19];
    const float* ln2_b  = (const float*)d_in[20];
    float* out = (float*)d_out;

    cudaFuncSetAttribute(k_pre, cudaFuncAttributeMaxDynamicSharedMemorySize, PRE_DSMEM);
    cudaFuncSetAttribute(k_ffn, cudaFuncAttributeMaxDynamicSharedMemorySize, K3_DSMEM);

    k_pre<<<7, 256, PRE_DSMEM>>>(ms, lin_w, lin_b, wq, wk, wv, bq, bk, bv,
                                 out_w, out_b, w1, w2);
    k_attn<<<N_SEG/8, 256>>>(roads, ln1_g, ln1_b, out);
    k_ffn<<<N_SEG/128, 256, K3_DSMEM>>>(b1, b2, ln2_g, ln2_b, out);
}

// round 13
// speedup vs baseline: 1.1610x; 1.0021x over previous
#include <cuda_runtime.h>
#include <cuda_bf16.h>
#include <math.h>
#include <stdint.h>

#define N_SEG 12800
#define D_ 128
#define S_ 100
#define B_ 16
#define M_ 8
#define P_ 40
#define OUT_ELEMS (S_*B_*M_*D_)   // 1638400
#define FULLMASK 0xffffffffu

#define LDT 136                    // padded bf16 row stride
#define TILE_E (128*LDT)           // 128-row tile elems
#define T_BYTES (TILE_E*2)         // 34816

// ---------------- folded weights + scratch ----------------
__device__ float g_score_w[24];     // [a*8+h]
__device__ float g_score_c[8];
__device__ float g_W2[24*128];      // [(h*3+a)*128 + j]
__device__ float g_c2[128];
__device__ float g_emb[N_SEG*D_];   // post-LN1 embeddings (6.5MB scratch)
// pre-split bf16 weight tiles [n][LDT]; pair w: [hi,lo]. w=0..2: w1 n-chunks, 3..5: w2 k-chunks
__device__ __align__(16) __nv_bfloat16 g_wb[6*2*TILE_E];

__device__ __forceinline__ unsigned pk2(float a, float b) {
    __nv_bfloat162 t = __floats2bfloat162_rn(a, b);
    return *reinterpret_cast<unsigned*>(&t);
}
__device__ __forceinline__ float blo(float x) {
    return x - __bfloat162float(__float2bfloat16(x));
}
__device__ __forceinline__ void mma16816(float* c, const uint32_t* a, uint32_t b0, uint32_t b1) {
    asm volatile("mma.sync.aligned.m16n8k16.row.col.f32.bf16.bf16.f32 "
        "{%0,%1,%2,%3}, {%4,%5,%6,%7}, {%8,%9}, {%0,%1,%2,%3};"
        : "+f"(c[0]), "+f"(c[1]), "+f"(c[2]), "+f"(c[3])
        : "r"(a[0]), "r"(a[1]), "r"(a[2]), "r"(a[3]), "r"(b0), "r"(b1));
}
__device__ __forceinline__ void ldsm4(uint32_t* r, uint32_t addr) {
    asm volatile("ldmatrix.sync.aligned.m8n8.x4.shared.b16 {%0,%1,%2,%3}, [%4];"
        : "=r"(r[0]), "=r"(r[1]), "=r"(r[2]), "=r"(r[3]) : "r"(addr));
}
__device__ __forceinline__ void cpa16(uint32_t daddr, const void* g) {
    asm volatile("cp.async.cg.shared.global [%0], [%1], 16;" :: "r"(daddr), "l"(g));
}
__device__ __forceinline__ void cpa_commit() {
    asm volatile("cp.async.commit_group;" ::: "memory");
}
template<int N> __device__ __forceinline__ void cpa_waitg() {
    asm volatile("cp.async.wait_group %0;" :: "n"(N) : "memory");
}

// ================= kernel 1: weight split (6 blocks, smem-staged) + fold (block 6) =================
#define PRE_DSMEM (192*1024)

__global__ void k_pre(const float* __restrict__ ms,   const float* __restrict__ lin_w,
                      const float* __restrict__ lin_b,const float* __restrict__ wq,
                      const float* __restrict__ wk,   const float* __restrict__ wv,
                      const float* __restrict__ bq,   const float* __restrict__ bk,
                      const float* __restrict__ bv,   const float* __restrict__ out_w,
                      const float* __restrict__ out_b,
                      const float* __restrict__ w1,   const float* __restrict__ w2)
{
    const int t = threadIdx.x;
    if (blockIdx.x < 6) {
        // -------- split: stage fp32 chunk [k][n] coalesced, emit [n][k] bf16 hi/lo --------
        extern __shared__ float Wst[];          // 128x128 fp32
        const int w = blockIdx.x;
        const uint32_t wsb = (uint32_t)__cvta_generic_to_shared(Wst);
        // coalesced reads: row k of the chunk (n contiguous)
        for (int i = t; i < 128*32; i += 256) {
            int k = i >> 5, n4 = (i & 31) << 2;
            const float* src = (w < 3) ? &w1[k*384 + w*128 + n4]
                                       : &w2[((w-3)*128 + k)*128 + n4];
            cpa16(wsb + (k*128 + n4)*4, src);
        }
        cpa_commit(); cpa_waitg<0>();
        __syncthreads();

        __nv_bfloat16* dh = g_wb + (w*2+0)*TILE_E;
        __nv_bfloat16* dl = g_wb + (w*2+1)*TILE_E;
        const int n  = t >> 1;
        const int kb = (t & 1) * 64;
        uint4* dh4 = reinterpret_cast<uint4*>(dh + n*LDT + kb);
        uint4* dl4 = reinterpret_cast<uint4*>(dl + n*LDT + kb);
        // 64 k-values per thread: 8 uint4 stores x 8 k each
        #pragma unroll
        for (int g = 0; g < 8; g++) {
            uint32_t h4[4], l4[4];
            #pragma unroll
            for (int j = 0; j < 4; j++) {
                const int k = kb + g*8 + j*2;
                float f0 = Wst[(k+0)*128 + n];
                float f1 = Wst[(k+1)*128 + n];
                __nv_bfloat16 h0 = __float2bfloat16(f0), h1 = __float2bfloat16(f1);
                h4[j] = (uint32_t)*(uint16_t*)&h0 | ((uint32_t)*(uint16_t*)&h1 << 16);
                l4[j] = pk2(f0 - __bfloat162float(h0), f1 - __bfloat162float(h1));
            }
            dh4[g] = make_uint4(h4[0], h4[1], h4[2], h4[3]);
            dl4[g] = make_uint4(l4[0], l4[1], l4[2], l4[3]);
        }
        return;
    }

    // -------- block 6: fold attention weights (cp.async pipelined) --------
    extern __shared__ float W[];    // 3 x 16384 floats
    float* W0 = W;
    float* W1 = W + 16384;
    float* Wv = W + 32768;
    __shared__ float q[128];
    __shared__ float wkq[128*8];
    __shared__ float lwv[3*128];
    __shared__ float cv[128];
    __shared__ float ms_s[128], lb_s[128];

    const uint32_t wsb = (uint32_t)__cvta_generic_to_shared(W);
    if (t < 128) { ms_s[t] = ms[t]; lb_s[t] = lin_b[t]; }

    for (int i = t; i < 4096; i += 256) cpa16(wsb + i*16, (const char*)wq + i*16);
    cpa_commit();
    for (int i = t; i < 4096; i += 256) cpa16(wsb + 65536 + i*16, (const char*)wk + i*16);
    cpa_commit();
    for (int i = t; i < 4096; i += 256) cpa16(wsb + 131072 + i*16, (const char*)wv + i*16);
    cpa_commit();

    cpa_waitg<2>();
    __syncthreads();
    if (t < 128) {
        float acc = bq[t];
        #pragma unroll 8
        for (int e = 0; e < 128; e++) acc += ms_s[e]*W0[e*128+t];
        q[t] = acc;
    }
    __syncthreads();

    for (int i = t; i < 4096; i += 256) cpa16(wsb + i*16, (const char*)out_w + i*16);
    cpa_commit();

    cpa_waitg<2>();
    __syncthreads();
    if (t < 128) {
        #pragma unroll
        for (int h = 0; h < 8; h++) {
            float s = 0.f;
            #pragma unroll
            for (int j = 0; j < 16; j++) s += W1[t*128 + h*16 + j]*q[h*16 + j];
            wkq[t*8 + h] = s;
        }
    }
    __syncthreads();

    if (t < 24) {
        int a = t/8, h = t%8;
        float s = 0.f;
        #pragma unroll 8
        for (int d = 0; d < 128; d++) s += lin_w[a*128+d]*wkq[d*8+h];
        g_score_w[a*8+h] = 0.25f*s;
    } else if (t < 32) {
        int h = t-24;
        float s = 0.f;
        #pragma unroll 8
        for (int d = 0; d < 128; d++) s += lb_s[d]*wkq[d*8+h];
        #pragma unroll
        for (int j = 0; j < 16; j++) s += q[h*16+j]*bk[h*16+j];
        g_score_c[h] = 0.25f*s;
    }

    cpa_waitg<1>();
    __syncthreads();
    if (t < 128) {
        float s0=0.f, s1=0.f, s2=0.f, sc=0.f;
        #pragma unroll 8
        for (int e = 0; e < 128; e++) {
            float w = Wv[e*128 + t];
            s0 += lin_w[0*128+e]*w;
            s1 += lin_w[1*128+e]*w;
            s2 += lin_w[2*128+e]*w;
            sc += lb_s[e]*w;
        }
        lwv[0*128+t]=s0; lwv[1*128+t]=s1; lwv[2*128+t]=s2;
        cv[t] = sc + bv[t];
    }
    cpa_waitg<0>();
    __syncthreads();
    if (t < 128) {
        #pragma unroll
        for (int h = 0; h < 8; h++)
            #pragma unroll
            for (int a = 0; a < 3; a++) {
                float s = 0.f;
                #pragma unroll
                for (int dd = 0; dd < 16; dd++) {
                    int d = h*16 + dd;
                    s += lwv[a*128+d]*W0[d*128+t];
                }
                g_W2[(h*3+a)*128 + t] = s;
            }
        float s = out_b[t];
        #pragma unroll 8
        for (int d = 0; d < 128; d++) s += cv[d]*W0[d*128+t];
        g_c2[t] = s;
    }
}

// ================= kernel 2: attention pooling + LN1 (1 seg/warp) =================
__global__ void k_attn(const float* __restrict__ roads,
                       const float* __restrict__ ln1_g, const float* __restrict__ ln1_b,
                       float* __restrict__ d_out)
{
    const int n    = (blockIdx.x*blockDim.x + threadIdx.x) >> 5;
    const int lane = threadIdx.x & 31;
    if (n >= N_SEG) return;

    const float4* rp = reinterpret_cast<const float4*>(roads) + n*P_;
    float4 a0 = rp[lane];
    float4 a1 = make_float4(0.f,0.f,0.f,0.f);
    if (lane < 8) a1 = rp[32 + lane];

    bool v0 = (a0.w != 0.0f);
    bool v1 = (lane < 8) && (a1.w != 0.0f);
    unsigned bm0 = __ballot_sync(FULLMASK, v0);
    unsigned bm1 = __ballot_sync(FULLMASK, v1);
    const bool seg_empty = ((bm0 | bm1) == 0u);
    if (seg_empty && lane == 0) v0 = true;

    float pa[24];
    #pragma unroll
    for (int h = 0; h < 8; h++) {
        const float sw0 = __ldg(&g_score_w[0*8+h]);
        const float sw1 = __ldg(&g_score_w[1*8+h]);
        const float sw2 = __ldg(&g_score_w[2*8+h]);
        const float sc  = __ldg(&g_score_c[h]);
        float s0 = sc + a0.x*sw0 + a0.y*sw1 + a0.z*sw2;
        float s1 = sc + a1.x*sw0 + a1.y*sw1 + a1.z*sw2;
        float mx = fmaxf(v0 ? s0 : -1e30f, v1 ? s1 : -1e30f);
        #pragma unroll
        for (int o = 16; o; o >>= 1) mx = fmaxf(mx, __shfl_xor_sync(FULLMASK, mx, o));
        float e0 = v0 ? __expf(s0 - mx) : 0.0f;
        float e1 = v1 ? __expf(s1 - mx) : 0.0f;
        float t0 = e0 + e1;
        float t1 = e0*a0.x + e1*a1.x;
        float t2 = e0*a0.y + e1*a1.y;
        float t3 = e0*a0.z + e1*a1.z;
        #pragma unroll
        for (int o = 16; o; o >>= 1) {
            t0 += __shfl_xor_sync(FULLMASK, t0, o);
            t1 += __shfl_xor_sync(FULLMASK, t1, o);
            t2 += __shfl_xor_sync(FULLMASK, t2, o);
            t3 += __shfl_xor_sync(FULLMASK, t3, o);
        }
        float inv = 1.0f / t0;
        pa[h*3+0] = t1*inv;
        pa[h*3+1] = t2*inv;
        pa[h*3+2] = t3*inv;
    }

    float y[4];
    #pragma unroll
    for (int u = 0; u < 4; u++) {
        int j = lane + 32*u;
        float acc = __ldg(&g_c2[j]);
        #pragma unroll
        for (int i = 0; i < 24; i++) acc += pa[i]*__ldg(&g_W2[i*128 + j]);
        y[u] = acc;
    }

    float loc = y[0]+y[1]+y[2]+y[3];
    #pragma unroll
    for (int o = 16; o; o >>= 1) loc += __shfl_xor_sync(FULLMASK, loc, o);
    const float mu = loc * (1.0f/128.0f);
    float sq = 0.f;
    #pragma unroll
    for (int u = 0; u < 4; u++) { float d = y[u]-mu; sq += d*d; }
    #pragma unroll
    for (int o = 16; o; o >>= 1) sq += __shfl_xor_sync(FULLMASK, sq, o);
    const float istd = rsqrtf(sq*(1.0f/128.0f) + 1e-5f);
    #pragma unroll
    for (int u = 0; u < 4; u++) {
        int j = lane + 32*u;
        g_emb[n*128 + j] = (y[u]-mu)*istd*__ldg(&ln1_g[j]) + __ldg(&ln1_b[j]);
    }

    if (lane == 0) d_out[OUT_ELEMS + n] = seg_empty ? 1.0f : 0.0f;
}

// ================= kernel 3: HMMA FFN (256 thr, warp m32 x n64) =================
#define K3_DSMEM (6*T_BYTES)    // 208896

__device__ __forceinline__ void gemm_pass(uint32_t aB, uint32_t bB, float (&acc)[2][8][4])
{
    #pragma unroll
    for (int k = 0; k < 8; k++) {
        uint32_t a0[4], a1[4];
        ldsm4(a0, aB + k*32);
        ldsm4(a1, aB + 16*LDT*2 + k*32);
        #pragma unroll
        for (int ntp = 0; ntp < 4; ntp++) {
            uint32_t b[4];
            ldsm4(b, bB + ntp*16*LDT*2 + k*32);
            mma16816(acc[0][2*ntp+0], a0, b[0], b[1]);
            mma16816(acc[1][2*ntp+0], a1, b[0], b[1]);
            mma16816(acc[0][2*ntp+1], a0, b[2], b[3]);
            mma16816(acc[1][2*ntp+1], a1, b[2], b[3]);
        }
    }
}

__global__ __launch_bounds__(256, 1)
void k_ffn(const float* __restrict__ b1, const float* __restrict__ b2,
           const float* __restrict__ ln2_g, const float* __restrict__ ln2_b,
           float* __restrict__ d_out)
{
    extern __shared__ __align__(16) char smem[];
    __nv_bfloat16* sAh = reinterpret_cast<__nv_bfloat16*>(smem);
    __nv_bfloat16* sAl = sAh + TILE_E;
    __nv_bfloat16* sHh = sAl + TILE_E;
    __nv_bfloat16* sHl = sHh + TILE_E;

    const uint32_t sb = (uint32_t)__cvta_generic_to_shared(smem);
    const uint32_t AH = sb, AL = AH + T_BYTES, HH = AL + T_BYTES,
                   HL = HH + T_BYTES, BH = HL + T_BYTES;

    const int tid  = threadIdx.x;
    const int wid  = tid >> 5;
    const int lane = tid & 31;
    const int qr   = lane >> 2;
    const int qc   = (lane & 3) << 1;
    const int mbase = (wid >> 1) * 32;
    const int nbase = (wid & 1) * 64;
    const int base  = blockIdx.x * 128;

    const uint32_t aoff = (uint32_t)(((lane & 15)*LDT + (lane >> 4)*8)*2 + mbase*LDT*2);
    const uint32_t boff = (uint32_t)((((lane & 7) + ((lane >> 4) << 3))*LDT
                                      + ((lane >> 3) & 1)*8)*2 + nbase*LDT*2);

    // stage W1(0)
    {
        const char* src = reinterpret_cast<const char*>(g_wb);
        for (int i = tid; i < 2*T_BYTES/16; i += 256) cpa16(BH + i*16, src + i*16);
        cpa_commit();
    }

    // block 0: seg_mask all_seg fix (flags written by k_attn)
    if (blockIdx.x == 0 && tid < 128) {
        float allm = 1.0f;
        #pragma unroll 4
        for (int s = 0; s < S_; s++)
            allm = fminf(allm, d_out[OUT_ELEMS + tid*S_ + s]);
        if (allm > 0.5f) d_out[OUT_ELEMS + tid*S_] = 0.0f;
    }

    // stage A = emb tile (bf16 hi/lo)
    {
        const float4* eb = reinterpret_cast<const float4*>(g_emb + base*128);
        for (int i = tid; i < 4096; i += 256) {
            int r = i >> 5, c4 = (i & 31) << 2;
            float4 v = eb[i];
            int off = r*LDT + c4;
            *reinterpret_cast<uint2*>(sAh + off) = make_uint2(pk2(v.x,v.y), pk2(v.z,v.w));
            *reinterpret_cast<uint2*>(sAl + off) =
                make_uint2(pk2(blo(v.x),blo(v.y)), pk2(blo(v.z),blo(v.w)));
        }
    }
    cpa_waitg<0>();
    __syncthreads();

    float acc2[2][8][4];
    #pragma unroll
    for (int mt = 0; mt < 2; mt++)
        #pragma unroll
        for (int nt = 0; nt < 8; nt++)
            #pragma unroll
            for (int c = 0; c < 4; c++) acc2[mt][nt][c] = 0.f;

    for (int kc = 0; kc < 3; kc++) {
        float acc1[2][8][4];
        #pragma unroll
        for (int mt = 0; mt < 2; mt++)
            #pragma unroll
            for (int nt = 0; nt < 8; nt++)
                #pragma unroll
                for (int c = 0; c < 4; c++) acc1[mt][nt][c] = 0.f;
        gemm_pass(AH + aoff, BH + boff, acc1);
        gemm_pass(AH + aoff, BH + T_BYTES + boff, acc1);
        gemm_pass(AL + aoff, BH + boff, acc1);

        // relu + bias + split -> H
        #pragma unroll
        for (int mt = 0; mt < 2; mt++)
            #pragma unroll
            for (int nt = 0; nt < 8; nt++) {
                const int row = mbase + mt*16 + qr;
                const int col = nbase + nt*8 + qc;
                const int cg  = kc*128 + col;
                float v0 = fmaxf(acc1[mt][nt][0] + __ldg(&b1[cg]),   0.f);
                float v1 = fmaxf(acc1[mt][nt][1] + __ldg(&b1[cg+1]), 0.f);
                float v2 = fmaxf(acc1[mt][nt][2] + __ldg(&b1[cg]),   0.f);
                float v3 = fmaxf(acc1[mt][nt][3] + __ldg(&b1[cg+1]), 0.f);
                *reinterpret_cast<uint32_t*>(sHh + row*LDT + col)     = pk2(v0, v1);
                *reinterpret_cast<uint32_t*>(sHl + row*LDT + col)     = pk2(blo(v0), blo(v1));
                *reinterpret_cast<uint32_t*>(sHh + (row+8)*LDT + col) = pk2(v2, v3);
                *reinterpret_cast<uint32_t*>(sHl + (row+8)*LDT + col) = pk2(blo(v2), blo(v3));
            }
        __syncthreads();

        // stage W2(kc)
        {
            const char* src = reinterpret_cast<const char*>(g_wb + (3+kc)*2*TILE_E);
            for (int i = tid; i < 2*T_BYTES/16; i += 256) cpa16(BH + i*16, src + i*16);
            cpa_commit(); cpa_waitg<0>();
        }
        __syncthreads();

        gemm_pass(HH + aoff, BH + boff, acc2);
        gemm_pass(HH + aoff, BH + T_BYTES + boff, acc2);
        gemm_pass(HL + aoff, BH + boff, acc2);

        if (kc < 2) {
            __syncthreads();
            const char* src = reinterpret_cast<const char*>(g_wb + (kc+1)*2*TILE_E);
            for (int i = tid; i < 2*T_BYTES/16; i += 256) cpa16(BH + i*16, src + i*16);
            cpa_commit(); cpa_waitg<0>();
            __syncthreads();
        }
    }
    __syncthreads();

    // dump acc2 + bias + residual into fp32 smem [128][132]
    float* sF = reinterpret_cast<float*>(smem);
    #pragma unroll
    for (int mt = 0; mt < 2; mt++)
        #pragma unroll
        for (int nt = 0; nt < 8; nt++) {
            const int row = mbase + mt*16 + qr;
            const int col = nbase + nt*8 + qc;
            const float2 e0 = *reinterpret_cast<const float2*>(&g_emb[(base+row)*128 + col]);
            const float2 e1 = *reinterpret_cast<const float2*>(&g_emb[(base+row+8)*128 + col]);
            const float bb0 = __ldg(&b2[col]), bb1 = __ldg(&b2[col+1]);
            sF[row*132 + col]       = acc2[mt][nt][0] + bb0 + e0.x;
            sF[row*132 + col + 1]   = acc2[mt][nt][1] + bb1 + e0.y;
            sF[(row+8)*132 + col]   = acc2[mt][nt][2] + bb0 + e1.x;
            sF[(row+8)*132 + col+1] = acc2[mt][nt][3] + bb1 + e1.y;
        }
    __syncthreads();

    // LN2 + transposed store (2 threads per row)
    {
        const int row = tid >> 1;
        const int sub = tid & 1;
        float sum = 0.f, sq = 0.f;
        #pragma unroll 8
        for (int c = sub*64; c < sub*64 + 64; c++) {
            float v = sF[row*132 + c];
            sum += v; sq += v*v;
        }
        sum += __shfl_xor_sync(FULLMASK, sum, 1);
        sq  += __shfl_xor_sync(FULLMASK, sq, 1);
        const float mu = sum * (1.0f/128.0f);
        const float istd = rsqrtf(sq*(1.0f/128.0f) - mu*mu + 1e-5f);

        const int n = base + row;
        const int s = n % S_;
        const int bm = n / S_;
        float* op = d_out + (((s*B_ + (bm >> 3))*M_ + (bm & 7)) << 7);
        #pragma unroll 4
        for (int c = sub*64; c < sub*64 + 64; c += 4) {
            float4 o4;
            o4.x = (sF[row*132+c+0]-mu)*istd*__ldg(&ln2_g[c+0]) + __ldg(&ln2_b[c+0]);
            o4.y = (sF[row*132+c+1]-mu)*istd*__ldg(&ln2_g[c+1]) + __ldg(&ln2_b[c+1]);
            o4.z = (sF[row*132+c+2]-mu)*istd*__ldg(&ln2_g[c+2]) + __ldg(&ln2_b[c+2]);
            o4.w = (sF[row*132+c+3]-mu)*istd*__ldg(&ln2_g[c+3]) + __ldg(&ln2_b[c+3]);
            *reinterpret_cast<float4*>(op + c) = o4;
        }
    }
}

// ================= launcher =================
extern "C" void kernel_launch(void* const* d_in, const int* in_sizes, int n_in,
                              void* d_out, int out_size)
{
    const float* roads  = (const float*)d_in[0];
    const float* ms     = (const float*)d_in[2];
    const float* lin_w  = (const float*)d_in[3];
    const float* lin_b  = (const float*)d_in[4];
    const float* wq     = (const float*)d_in[5];
    const float* wk     = (const float*)d_in[6];
    const float* wv     = (const float*)d_in[7];
    const float* bq     = (const float*)d_in[8];
    const float* bk     = (const float*)d_in[9];
    const float* bv     = (const float*)d_in[10];
    const float* out_w  = (const float*)d_in[11];
    const float* out_b  = (const float*)d_in[12];
    const float* ln1_g  = (const float*)d_in[13];
    const float* ln1_b  = (const float*)d_in[14];
    const float* w1     = (const float*)d_in[15];
    const float* b1     = (const float*)d_in[16];
    const float* w2     = (const float*)d_in[17];
    const float* b2     = (const float*)d_in[18];
    const float* ln2_g  = (const float*)d_in[19];
    const float* ln2_b  = (const float*)d_in[20];
    float* out = (float*)d_out;

    cudaFuncSetAttribute(k_pre, cudaFuncAttributeMaxDynamicSharedMemorySize, PRE_DSMEM);
    cudaFuncSetAttribute(k_ffn, cudaFuncAttributeMaxDynamicSharedMemorySize, K3_DSMEM);

    k_pre<<<7, 256, PRE_DSMEM>>>(ms, lin_w, lin_b, wq, wk, wv, bq, bk, bv,
                                 out_w, out_b, w1, w2);
    k_attn<<<N_SEG/8, 256>>>(roads, ln1_g, ln1_b, out);
    k_ffn<<<N_SEG/128, 256, K3_DSMEM>>>(b1, b2, ln2_g, ln2_b, out);
}

// round 15
// speedup vs baseline: 1.3089x; 1.1274x over previous
#include <cuda_runtime.h>
#include <cuda_bf16.h>
#include <math.h>
#include <stdint.h>

#define N_SEG 12800
#define D_ 128
#define S_ 100
#define B_ 16
#define M_ 8
#define P_ 40
#define OUT_ELEMS (S_*B_*M_*D_)   // 1638400
#define FULLMASK 0xffffffffu

#define LDT 136                    // padded bf16 row stride
#define TILE_E (128*LDT)           // 128-row tile elems
#define T_BYTES (TILE_E*2)         // 34816

// ---------------- folded weights + scratch ----------------
__device__ float g_score_w[24];
__device__ float g_score_c[8];
__device__ float g_W2[24*128];
__device__ float g_c2[128];
__device__ float g_emb[N_SEG*D_];                       // fp32 (residual)
__device__ __align__(16) __nv_bfloat16 g_embh[N_SEG*LDT];  // bf16 hi (padded)
__device__ __align__(16) __nv_bfloat16 g_embl[N_SEG*LDT];  // bf16 lo (padded)
// pre-split bf16 weight tiles [n][LDT]; pair w: [hi,lo]. w=0..2: w1 n-chunks, 3..5: w2 k-chunks
__device__ __align__(16) __nv_bfloat16 g_wb[6*2*TILE_E];

__device__ __forceinline__ unsigned pk2(float a, float b) {
    __nv_bfloat162 t = __floats2bfloat162_rn(a, b);
    return *reinterpret_cast<unsigned*>(&t);
}
__device__ __forceinline__ float blo(float x) {
    return x - __bfloat162float(__float2bfloat16(x));
}
__device__ __forceinline__ void mma16816(float* c, const uint32_t* a, uint32_t b0, uint32_t b1) {
    asm volatile("mma.sync.aligned.m16n8k16.row.col.f32.bf16.bf16.f32 "
        "{%0,%1,%2,%3}, {%4,%5,%6,%7}, {%8,%9}, {%0,%1,%2,%3};"
        : "+f"(c[0]), "+f"(c[1]), "+f"(c[2]), "+f"(c[3])
        : "r"(a[0]), "r"(a[1]), "r"(a[2]), "r"(a[3]), "r"(b0), "r"(b1));
}
__device__ __forceinline__ void ldsm4(uint32_t* r, uint32_t addr) {
    asm volatile("ldmatrix.sync.aligned.m8n8.x4.shared.b16 {%0,%1,%2,%3}, [%4];"
        : "=r"(r[0]), "=r"(r[1]), "=r"(r[2]), "=r"(r[3]) : "r"(addr));
}
__device__ __forceinline__ void cpa16(uint32_t daddr, const void* g) {
    asm volatile("cp.async.cg.shared.global [%0], [%1], 16;" :: "r"(daddr), "l"(g));
}
__device__ __forceinline__ void cpa_commit() {
    asm volatile("cp.async.commit_group;" ::: "memory");
}
template<int N> __device__ __forceinline__ void cpa_waitg() {
    asm volatile("cp.async.wait_group %0;" :: "n"(N) : "memory");
}

// ================= kernel 1: weight split (6 blocks, smem-staged) + fold (block 6) =================
#define PRE_DSMEM (192*1024)

__global__ void k_pre(const float* __restrict__ ms,   const float* __restrict__ lin_w,
                      const float* __restrict__ lin_b,const float* __restrict__ wq,
                      const float* __restrict__ wk,   const float* __restrict__ wv,
                      const float* __restrict__ bq,   const float* __restrict__ bk,
                      const float* __restrict__ bv,   const float* __restrict__ out_w,
                      const float* __restrict__ out_b,
                      const float* __restrict__ w1,   const float* __restrict__ w2)
{
    const int t = threadIdx.x;
    if (blockIdx.x < 6) {
        extern __shared__ float Wst[];          // 128x128 fp32
        const int w = blockIdx.x;
        const uint32_t wsb = (uint32_t)__cvta_generic_to_shared(Wst);
        for (int i = t; i < 128*32; i += 256) {
            int k = i >> 5, n4 = (i & 31) << 2;
            const float* src = (w < 3) ? &w1[k*384 + w*128 + n4]
                                       : &w2[((w-3)*128 + k)*128 + n4];
            cpa16(wsb + (k*128 + n4)*4, src);
        }
        cpa_commit(); cpa_waitg<0>();
        __syncthreads();

        __nv_bfloat16* dh = g_wb + (w*2+0)*TILE_E;
        __nv_bfloat16* dl = g_wb + (w*2+1)*TILE_E;
        const int n  = t >> 1;
        const int kb = (t & 1) * 64;
        uint4* dh4 = reinterpret_cast<uint4*>(dh + n*LDT + kb);
        uint4* dl4 = reinterpret_cast<uint4*>(dl + n*LDT + kb);
        #pragma unroll
        for (int g = 0; g < 8; g++) {
            uint32_t h4[4], l4[4];
            #pragma unroll
            for (int j = 0; j < 4; j++) {
                const int k = kb + g*8 + j*2;
                float f0 = Wst[(k+0)*128 + n];
                float f1 = Wst[(k+1)*128 + n];
                __nv_bfloat16 h0 = __float2bfloat16(f0), h1 = __float2bfloat16(f1);
                h4[j] = (uint32_t)*(uint16_t*)&h0 | ((uint32_t)*(uint16_t*)&h1 << 16);
                l4[j] = pk2(f0 - __bfloat162float(h0), f1 - __bfloat162float(h1));
            }
            dh4[g] = make_uint4(h4[0], h4[1], h4[2], h4[3]);
            dl4[g] = make_uint4(l4[0], l4[1], l4[2], l4[3]);
        }
        return;
    }

    // -------- block 6: fold attention weights (cp.async pipelined) --------
    extern __shared__ float W[];
    float* W0 = W;
    float* W1 = W + 16384;
    float* Wv = W + 32768;
    __shared__ float q[128];
    __shared__ float wkq[128*8];
    __shared__ float lwv[3*128];
    __shared__ float cv[128];
    __shared__ float ms_s[128], lb_s[128];

    const uint32_t wsb = (uint32_t)__cvta_generic_to_shared(W);
    if (t < 128) { ms_s[t] = ms[t]; lb_s[t] = lin_b[t]; }

    for (int i = t; i < 4096; i += 256) cpa16(wsb + i*16, (const char*)wq + i*16);
    cpa_commit();
    for (int i = t; i < 4096; i += 256) cpa16(wsb + 65536 + i*16, (const char*)wk + i*16);
    cpa_commit();
    for (int i = t; i < 4096; i += 256) cpa16(wsb + 131072 + i*16, (const char*)wv + i*16);
    cpa_commit();

    cpa_waitg<2>();
    __syncthreads();
    if (t < 128) {
        float acc = bq[t];
        #pragma unroll 8
        for (int e = 0; e < 128; e++) acc += ms_s[e]*W0[e*128+t];
        q[t] = acc;
    }
    __syncthreads();

    for (int i = t; i < 4096; i += 256) cpa16(wsb + i*16, (const char*)out_w + i*16);
    cpa_commit();

    cpa_waitg<2>();
    __syncthreads();
    if (t < 128) {
        #pragma unroll
        for (int h = 0; h < 8; h++) {
            float s = 0.f;
            #pragma unroll
            for (int j = 0; j < 16; j++) s += W1[t*128 + h*16 + j]*q[h*16 + j];
            wkq[t*8 + h] = s;
        }
    }
    __syncthreads();

    if (t < 24) {
        int a = t/8, h = t%8;
        float s = 0.f;
        #pragma unroll 8
        for (int d = 0; d < 128; d++) s += lin_w[a*128+d]*wkq[d*8+h];
        g_score_w[a*8+h] = 0.25f*s;
    } else if (t < 32) {
        int h = t-24;
        float s = 0.f;
        #pragma unroll 8
        for (int d = 0; d < 128; d++) s += lb_s[d]*wkq[d*8+h];
        #pragma unroll
        for (int j = 0; j < 16; j++) s += q[h*16+j]*bk[h*16+j];
        g_score_c[h] = 0.25f*s;
    }

    cpa_waitg<1>();
    __syncthreads();
    if (t < 128) {
        float s0=0.f, s1=0.f, s2=0.f, sc=0.f;
        #pragma unroll 8
        for (int e = 0; e < 128; e++) {
            float w = Wv[e*128 + t];
            s0 += lin_w[0*128+e]*w;
            s1 += lin_w[1*128+e]*w;
            s2 += lin_w[2*128+e]*w;
            sc += lb_s[e]*w;
        }
        lwv[0*128+t]=s0; lwv[1*128+t]=s1; lwv[2*128+t]=s2;
        cv[t] = sc + bv[t];
    }
    cpa_waitg<0>();
    __syncthreads();
    if (t < 128) {
        #pragma unroll
        for (int h = 0; h < 8; h++)
            #pragma unroll
            for (int a = 0; a < 3; a++) {
                float s = 0.f;
                #pragma unroll
                for (int dd = 0; dd < 16; dd++) {
                    int d = h*16 + dd;
                    s += lwv[a*128+d]*W0[d*128+t];
                }
                g_W2[(h*3+a)*128 + t] = s;
            }
        float s = out_b[t];
        #pragma unroll 8
        for (int d = 0; d < 128; d++) s += cv[d]*W0[d*128+t];
        g_c2[t] = s;
    }
}

// ================= kernel 2: attention + LN1 + bf16 hi/lo emit (1 seg/warp) =================
__global__ void k_attn(const float* __restrict__ roads,
                       const float* __restrict__ ln1_g, const float* __restrict__ ln1_b,
                       float* __restrict__ d_out)
{
    const int n    = (blockIdx.x*blockDim.x + threadIdx.x) >> 5;
    const int lane = threadIdx.x & 31;
    if (n >= N_SEG) return;

    const float4* rp = reinterpret_cast<const float4*>(roads) + n*P_;
    float4 a0 = rp[lane];
    float4 a1 = make_float4(0.f,0.f,0.f,0.f);
    if (lane < 8) a1 = rp[32 + lane];

    bool v0 = (a0.w != 0.0f);
    bool v1 = (lane < 8) && (a1.w != 0.0f);
    unsigned bm0 = __ballot_sync(FULLMASK, v0);
    unsigned bm1 = __ballot_sync(FULLMASK, v1);
    const bool seg_empty = ((bm0 | bm1) == 0u);
    if (seg_empty && lane == 0) v0 = true;

    float pa[24];
    #pragma unroll
    for (int h = 0; h < 8; h++) {
        const float sw0 = __ldg(&g_score_w[0*8+h]);
        const float sw1 = __ldg(&g_score_w[1*8+h]);
        const float sw2 = __ldg(&g_score_w[2*8+h]);
        const float sc  = __ldg(&g_score_c[h]);
        float s0 = sc + a0.x*sw0 + a0.y*sw1 + a0.z*sw2;
        float s1 = sc + a1.x*sw0 + a1.y*sw1 + a1.z*sw2;
        float mx = fmaxf(v0 ? s0 : -1e30f, v1 ? s1 : -1e30f);
        #pragma unroll
        for (int o = 16; o; o >>= 1) mx = fmaxf(mx, __shfl_xor_sync(FULLMASK, mx, o));
        float e0 = v0 ? __expf(s0 - mx) : 0.0f;
        float e1 = v1 ? __expf(s1 - mx) : 0.0f;
        float t0 = e0 + e1;
        float t1 = e0*a0.x + e1*a1.x;
        float t2 = e0*a0.y + e1*a1.y;
        float t3 = e0*a0.z + e1*a1.z;
        #pragma unroll
        for (int o = 16; o; o >>= 1) {
            t0 += __shfl_xor_sync(FULLMASK, t0, o);
            t1 += __shfl_xor_sync(FULLMASK, t1, o);
            t2 += __shfl_xor_sync(FULLMASK, t2, o);
            t3 += __shfl_xor_sync(FULLMASK, t3, o);
        }
        float inv = 1.0f / t0;
        pa[h*3+0] = t1*inv;
        pa[h*3+1] = t2*inv;
        pa[h*3+2] = t3*inv;
    }

    float y[4];
    #pragma unroll
    for (int u = 0; u < 4; u++) {
        int j = lane + 32*u;
        float acc = __ldg(&g_c2[j]);
        #pragma unroll
        for (int i = 0; i < 24; i++) acc += pa[i]*__ldg(&g_W2[i*128 + j]);
        y[u] = acc;
    }

    float loc = y[0]+y[1]+y[2]+y[3];
    #pragma unroll
    for (int o = 16; o; o >>= 1) loc += __shfl_xor_sync(FULLMASK, loc, o);
    const float mu = loc * (1.0f/128.0f);
    float sq = 0.f;
    #pragma unroll
    for (int u = 0; u < 4; u++) { float d = y[u]-mu; sq += d*d; }
    #pragma unroll
    for (int o = 16; o; o >>= 1) sq += __shfl_xor_sync(FULLMASK, sq, o);
    const float istd = rsqrtf(sq*(1.0f/128.0f) + 1e-5f);
    #pragma unroll
    for (int u = 0; u < 4; u++) {
        int j = lane + 32*u;
        float e = (y[u]-mu)*istd*__ldg(&ln1_g[j]) + __ldg(&ln1_b[j]);
        g_emb[n*128 + j] = e;
        __nv_bfloat16 h = __float2bfloat16(e);
        g_embh[n*LDT + j] = h;
        g_embl[n*LDT + j] = __float2bfloat16(e - __bfloat162float(h));
    }

    if (lane == 0) d_out[OUT_ELEMS + n] = seg_empty ? 1.0f : 0.0f;
}

// ================= kernel 3: HMMA FFN, pipelined weight staging =================
#define K3_DSMEM (6*T_BYTES)    // 208896

__device__ __forceinline__ void gemm_pass(uint32_t aB, uint32_t bB, float (&acc)[2][8][4])
{
    #pragma unroll
    for (int k = 0; k < 8; k++) {
        uint32_t a0[4], a1[4];
        ldsm4(a0, aB + k*32);
        ldsm4(a1, aB + 16*LDT*2 + k*32);
        #pragma unroll
        for (int ntp = 0; ntp < 4; ntp++) {
            uint32_t b[4];
            ldsm4(b, bB + ntp*16*LDT*2 + k*32);
            mma16816(acc[0][2*ntp+0], a0, b[0], b[1]);
            mma16816(acc[1][2*ntp+0], a1, b[0], b[1]);
            mma16816(acc[0][2*ntp+1], a0, b[2], b[3]);
            mma16816(acc[1][2*ntp+1], a1, b[2], b[3]);
        }
    }
}

// stage one 34816B weight tile (hi or lo) into smem buffer
__device__ __forceinline__ void stage_w(uint32_t dst, const __nv_bfloat16* src, int tid) {
    const char* s = reinterpret_cast<const char*>(src);
    for (int i = tid; i < T_BYTES/16; i += 256) cpa16(dst + i*16, s + i*16);
    cpa_commit();
}

__global__ __launch_bounds__(256, 1)
void k_ffn(const float* __restrict__ b1, const float* __restrict__ b2,
           const float* __restrict__ ln2_g, const float* __restrict__ ln2_b,
           float* __restrict__ d_out)
{
    extern __shared__ __align__(16) char smem[];
    __nv_bfloat16* sHh = reinterpret_cast<__nv_bfloat16*>(smem) + 2*TILE_E;
    __nv_bfloat16* sHl = sHh + TILE_E;

    const uint32_t sb = (uint32_t)__cvta_generic_to_shared(smem);
    const uint32_t AH = sb, AL = AH + T_BYTES, HH = AL + T_BYTES,
                   HL = HH + T_BYTES, BX = HL + T_BYTES, BY = BX + T_BYTES;

    const int tid  = threadIdx.x;
    const int wid  = tid >> 5;
    const int lane = tid & 31;
    const int qr   = lane >> 2;
    const int qc   = (lane & 3) << 1;
    const int mbase = (wid >> 1) * 32;
    const int nbase = (wid & 1) * 64;
    const int base  = blockIdx.x * 128;

    const uint32_t aoff = (uint32_t)(((lane & 15)*LDT + (lane >> 4)*8)*2 + mbase*LDT*2);
    const uint32_t boff = (uint32_t)((((lane & 7) + ((lane >> 4) << 3))*LDT
                                      + ((lane >> 3) & 1)*8)*2 + nbase*LDT*2);

    // ---- prologue: A(hi/lo) + W1(0) hi/lo, one cp.async group ----
    {
        const char* eh = reinterpret_cast<const char*>(g_embh + base*LDT);
        const char* el = reinterpret_cast<const char*>(g_embl + base*LDT);
        for (int i = tid; i < 2048; i += 256) {
            int row = i >> 4, c = (i & 15) << 4;   // 16B chunk within 256B of used row
            cpa16(AH + (uint32_t)(row*LDT*2) + c, eh + row*LDT*2 + c);
            cpa16(AL + (uint32_t)(row*LDT*2) + c, el + row*LDT*2 + c);
        }
        const char* s = reinterpret_cast<const char*>(g_wb);
        for (int i = tid; i < 2*T_BYTES/16; i += 256) cpa16(BX + i*16, s + i*16);
        cpa_commit();
    }

    // block 0: seg_mask all_seg fix (flags written by k_attn)
    if (blockIdx.x == 0 && tid < 128) {
        float allm = 1.0f;
        #pragma unroll 4
        for (int s = 0; s < S_; s++)
            allm = fminf(allm, d_out[OUT_ELEMS + tid*S_ + s]);
        if (allm > 0.5f) d_out[OUT_ELEMS + tid*S_] = 0.0f;
    }

    cpa_waitg<0>();
    __syncthreads();

    float acc2[2][8][4];
    #pragma unroll
    for (int mt = 0; mt < 2; mt++)
        #pragma unroll
        for (int nt = 0; nt < 8; nt++)
            #pragma unroll
            for (int c = 0; c < 4; c++) acc2[mt][nt][c] = 0.f;

    for (int kc = 0; kc < 3; kc++) {
        // entry: BX = W1hi(kc), BY = W1lo(kc)
        float acc1[2][8][4];
        #pragma unroll
        for (int mt = 0; mt < 2; mt++)
            #pragma unroll
            for (int nt = 0; nt < 8; nt++)
                #pragma unroll
                for (int c = 0; c < 4; c++) acc1[mt][nt][c] = 0.f;

        gemm_pass(AH + aoff, BX + boff, acc1);
        gemm_pass(AH + aoff, BY + boff, acc1);
        __syncthreads();                                   // BY free
        stage_w(BY, g_wb + (3+kc)*2*TILE_E, tid);          // W2hi(kc) -> BY (overlaps next pass)
        gemm_pass(AL + aoff, BX + boff, acc1);

        // relu + bias + split -> H
        #pragma unroll
        for (int mt = 0; mt < 2; mt++)
            #pragma unroll
            for (int nt = 0; nt < 8; nt++) {
                const int row = mbase + mt*16 + qr;
                const int col = nbase + nt*8 + qc;
                const int cg  = kc*128 + col;
                float v0 = fmaxf(acc1[mt][nt][0] + __ldg(&b1[cg]),   0.f);
                float v1 = fmaxf(acc1[mt][nt][1] + __ldg(&b1[cg+1]), 0.f);
                float v2 = fmaxf(acc1[mt][nt][2] + __ldg(&b1[cg]),   0.f);
                float v3 = fmaxf(acc1[mt][nt][3] + __ldg(&b1[cg+1]), 0.f);
                *reinterpret_cast<uint32_t*>(sHh + row*LDT + col)     = pk2(v0, v1);
                *reinterpret_cast<uint32_t*>(sHl + row*LDT + col)     = pk2(blo(v0), blo(v1));
                *reinterpret_cast<uint32_t*>(sHh + (row+8)*LDT + col) = pk2(v2, v3);
                *reinterpret_cast<uint32_t*>(sHl + (row+8)*LDT + col) = pk2(blo(v2), blo(v3));
            }
        cpa_waitg<0>();
        __syncthreads();                                   // H + BY(W2hi) ready; BX free
        stage_w(BX, g_wb + ((3+kc)*2+1)*TILE_E, tid);      // W2lo(kc) -> BX (overlaps next pass)
        gemm_pass(HH + aoff, BY + boff, acc2);
        cpa_waitg<0>();
        __syncthreads();                                   // BX(W2lo) ready
        gemm_pass(HH + aoff, BX + boff, acc2);
        gemm_pass(HL + aoff, BY + boff, acc2);

        if (kc < 2) {
            __syncthreads();                               // BX,BY free
            stage_w(BX, g_wb + (kc+1)*2*TILE_E, tid);      // W1hi(kc+1)
            stage_w(BY, g_wb + ((kc+1)*2+1)*TILE_E, tid);  // W1lo(kc+1)
            cpa_waitg<0>();
            __syncthreads();
        }
    }
    __syncthreads();

    // dump acc2 + bias + residual into fp32 smem [128][132]
    float* sF = reinterpret_cast<float*>(smem);
    #pragma unroll
    for (int mt = 0; mt < 2; mt++)
        #pragma unroll
        for (int nt = 0; nt < 8; nt++) {
            const int row = mbase + mt*16 + qr;
            const int col = nbase + nt*8 + qc;
            const float2 e0 = *reinterpret_cast<const float2*>(&g_emb[(base+row)*128 + col]);
            const float2 e1 = *reinterpret_cast<const float2*>(&g_emb[(base+row+8)*128 + col]);
            const float bb0 = __ldg(&b2[col]), bb1 = __ldg(&b2[col+1]);
            sF[row*132 + col]       = acc2[mt][nt][0] + bb0 + e0.x;
            sF[row*132 + col + 1]   = acc2[mt][nt][1] + bb1 + e0.y;
            sF[(row+8)*132 + col]   = acc2[mt][nt][2] + bb0 + e1.x;
            sF[(row+8)*132 + col+1] = acc2[mt][nt][3] + bb1 + e1.y;
        }
    __syncthreads();

    // LN2 + transposed store (2 threads per row)
    {
        const int row = tid >> 1;
        const int sub = tid & 1;
        float sum = 0.f, sq = 0.f;
        #pragma unroll 8
        for (int c = sub*64; c < sub*64 + 64; c++) {
            float v = sF[row*132 + c];
            sum += v; sq += v*v;
        }
        sum += __shfl_xor_sync(FULLMASK, sum, 1);
        sq  += __shfl_xor_sync(FULLMASK, sq, 1);
        const float mu = sum * (1.0f/128.0f);
        const float istd = rsqrtf(sq*(1.0f/128.0f) - mu*mu + 1e-5f);

        const int n = base + row;
        const int s = n % S_;
        const int bm = n / S_;
        float* op = d_out + (((s*B_ + (bm >> 3))*M_ + (bm & 7)) << 7);
        #pragma unroll 4
        for (int c = sub*64; c < sub*64 + 64; c += 4) {
            float4 o4;
            o4.x = (sF[row*132+c+0]-mu)*istd*__ldg(&ln2_g[c+0]) + __ldg(&ln2_b[c+0]);
            o4.y = (sF[row*132+c+1]-mu)*istd*__ldg(&ln2_g[c+1]) + __ldg(&ln2_b[c+1]);
            o4.z = (sF[row*132+c+2]-mu)*istd*__ldg(&ln2_g[c+2]) + __ldg(&ln2_b[c+2]);
            o4.w = (sF[row*132+c+3]-mu)*istd*__ldg(&ln2_g[c+3]) + __ldg(&ln2_b[c+3]);
            *reinterpret_cast<float4*>(op + c) = o4;
        }
    }
}

// ================= launcher =================
extern "C" void kernel_launch(void* const* d_in, const int* in_sizes, int n_in,
                              void* d_out, int out_size)
{
    const float* roads  = (const float*)d_in[0];
    const float* ms     = (const float*)d_in[2];
    const float* lin_w  = (const float*)d_in[3];
    const float* lin_b  = (const float*)d_in[4];
    const float* wq     = (const float*)d_in[5];
    const float* wk     = (const float*)d_in[6];
    const float* wv     = (const float*)d_in[7];
    const float* bq     = (const float*)d_in[8];
    const float* bk     = (const float*)d_in[9];
    const float* bv     = (const float*)d_in[10];
    const float* out_w  = (const float*)d_in[11];
    const float* out_b  = (const float*)d_in[12];
    const float* ln1_g  = (const float*)d_in[13];
    const float* ln1_b  = (const float*)d_in[14];
    const float* w1     = (const float*)d_in[15];
    const float* b1     = (const float*)d_in[16];
    const float* w2     = (const float*)d_in[17];
    const float* b2     = (const float*)d_in[18];
    const float* ln2_g  = (const float*)d_in[19];
    const float* ln2_b  = (const float*)d_in[20];
    float* out = (float*)d_out;

    cudaFuncSetAttribute(k_pre, cudaFuncAttributeMaxDynamicSharedMemorySize, PRE_DSMEM);
    cudaFuncSetAttribute(k_ffn, cudaFuncAttributeMaxDynamicSharedMemorySize, K3_DSMEM);

    k_pre<<<7, 256, PRE_DSMEM>>>(ms, lin_w, lin_b, wq, wk, wv, bq, bk, bv,
                                 out_w, out_b, w1, w2);
    k_attn<<<N_SEG/8, 256>>>(roads, ln1_g, ln1_b, out);
    k_ffn<<<N_SEG/128, 256, K3_DSMEM>>>(b1, b2, ln2_g, ln2_b, out);
}

// round 16
// speedup vs baseline: 1.4265x; 1.0898x over previous
#include <cuda_runtime.h>
#include <cuda_bf16.h>
#include <math.h>
#include <stdint.h>

#define N_SEG 12800
#define D_ 128
#define S_ 100
#define B_ 16
#define M_ 8
#define P_ 40
#define OUT_ELEMS (S_*B_*M_*D_)   // 1638400
#define FULLMASK 0xffffffffu

#define LDT 136                    // padded bf16 row stride
#define TILE_E (128*LDT)           // 128-row weight tile elems
#define T_BYTES (TILE_E*2)         // 34816

#define ROWS 96                    // rows per ffn block
#define NBLK 134                   // ceil(12800/96)
#define AT_B (ROWS*LDT*2)          // 26112 bytes per 96-row tile

// ---------------- folded weights + scratch (padded +64 rows for ragged last block) ----------------
__device__ float g_score_w[24];
__device__ float g_score_c[8];
__device__ float g_W2[24*128];
__device__ float g_c2[128];
__device__ float g_emb[(N_SEG+64)*D_];
__device__ __align__(16) __nv_bfloat16 g_embh[(N_SEG+64)*LDT];
__device__ __align__(16) __nv_bfloat16 g_embl[(N_SEG+64)*LDT];
__device__ __align__(16) __nv_bfloat16 g_wb[6*2*TILE_E];

__device__ __forceinline__ unsigned pk2(float a, float b) {
    __nv_bfloat162 t = __floats2bfloat162_rn(a, b);
    return *reinterpret_cast<unsigned*>(&t);
}
__device__ __forceinline__ float blo(float x) {
    return x - __bfloat162float(__float2bfloat16(x));
}
__device__ __forceinline__ void mma16816(float* c, const uint32_t* a, uint32_t b0, uint32_t b1) {
    asm volatile("mma.sync.aligned.m16n8k16.row.col.f32.bf16.bf16.f32 "
        "{%0,%1,%2,%3}, {%4,%5,%6,%7}, {%8,%9}, {%0,%1,%2,%3};"
        : "+f"(c[0]), "+f"(c[1]), "+f"(c[2]), "+f"(c[3])
        : "r"(a[0]), "r"(a[1]), "r"(a[2]), "r"(a[3]), "r"(b0), "r"(b1));
}
__device__ __forceinline__ void ldsm4(uint32_t* r, uint32_t addr) {
    asm volatile("ldmatrix.sync.aligned.m8n8.x4.shared.b16 {%0,%1,%2,%3}, [%4];"
        : "=r"(r[0]), "=r"(r[1]), "=r"(r[2]), "=r"(r[3]) : "r"(addr));
}
__device__ __forceinline__ void cpa16(uint32_t daddr, const void* g) {
    asm volatile("cp.async.cg.shared.global [%0], [%1], 16;" :: "r"(daddr), "l"(g));
}
__device__ __forceinline__ void cpa_commit() {
    asm volatile("cp.async.commit_group;" ::: "memory");
}
template<int N> __device__ __forceinline__ void cpa_waitg() {
    asm volatile("cp.async.wait_group %0;" :: "n"(N) : "memory");
}

// ================= kernel 1: weight split (6 blocks, smem-staged) + fold (block 6) =================
#define PRE_DSMEM (192*1024)

__global__ void k_pre(const float* __restrict__ ms,   const float* __restrict__ lin_w,
                      const float* __restrict__ lin_b,const float* __restrict__ wq,
                      const float* __restrict__ wk,   const float* __restrict__ wv,
                      const float* __restrict__ bq,   const float* __restrict__ bk,
                      const float* __restrict__ bv,   const float* __restrict__ out_w,
                      const float* __restrict__ out_b,
                      const float* __restrict__ w1,   const float* __restrict__ w2)
{
    const int t = threadIdx.x;
    if (blockIdx.x < 6) {
        extern __shared__ float Wst[];          // 128x128 fp32
        const int w = blockIdx.x;
        const uint32_t wsb = (uint32_t)__cvta_generic_to_shared(Wst);
        for (int i = t; i < 128*32; i += 256) {
            int k = i >> 5, n4 = (i & 31) << 2;
            const float* src = (w < 3) ? &w1[k*384 + w*128 + n4]
                                       : &w2[((w-3)*128 + k)*128 + n4];
            cpa16(wsb + (k*128 + n4)*4, src);
        }
        cpa_commit(); cpa_waitg<0>();
        __syncthreads();

        __nv_bfloat16* dh = g_wb + (w*2+0)*TILE_E;
        __nv_bfloat16* dl = g_wb + (w*2+1)*TILE_E;
        const int n  = t >> 1;
        const int kb = (t & 1) * 64;
        uint4* dh4 = reinterpret_cast<uint4*>(dh + n*LDT + kb);
        uint4* dl4 = reinterpret_cast<uint4*>(dl + n*LDT + kb);
        #pragma unroll
        for (int g = 0; g < 8; g++) {
            uint32_t h4[4], l4[4];
            #pragma unroll
            for (int j = 0; j < 4; j++) {
                const int k = kb + g*8 + j*2;
                float f0 = Wst[(k+0)*128 + n];
                float f1 = Wst[(k+1)*128 + n];
                __nv_bfloat16 h0 = __float2bfloat16(f0), h1 = __float2bfloat16(f1);
                h4[j] = (uint32_t)*(uint16_t*)&h0 | ((uint32_t)*(uint16_t*)&h1 << 16);
                l4[j] = pk2(f0 - __bfloat162float(h0), f1 - __bfloat162float(h1));
            }
            dh4[g] = make_uint4(h4[0], h4[1], h4[2], h4[3]);
            dl4[g] = make_uint4(l4[0], l4[1], l4[2], l4[3]);
        }
        return;
    }

    // -------- block 6: fold attention weights (cp.async pipelined) --------
    extern __shared__ float W[];
    float* W0 = W;
    float* W1 = W + 16384;
    float* Wv = W + 32768;
    __shared__ float q[128];
    __shared__ float wkq[128*8];
    __shared__ float lwv[3*128];
    __shared__ float cv[128];
    __shared__ float ms_s[128], lb_s[128];

    const uint32_t wsb = (uint32_t)__cvta_generic_to_shared(W);
    if (t < 128) { ms_s[t] = ms[t]; lb_s[t] = lin_b[t]; }

    for (int i = t; i < 4096; i += 256) cpa16(wsb + i*16, (const char*)wq + i*16);
    cpa_commit();
    for (int i = t; i < 4096; i += 256) cpa16(wsb + 65536 + i*16, (const char*)wk + i*16);
    cpa_commit();
    for (int i = t; i < 4096; i += 256) cpa16(wsb + 131072 + i*16, (const char*)wv + i*16);
    cpa_commit();

    cpa_waitg<2>();
    __syncthreads();
    if (t < 128) {
        float acc = bq[t];
        #pragma unroll 8
        for (int e = 0; e < 128; e++) acc += ms_s[e]*W0[e*128+t];
        q[t] = acc;
    }
    __syncthreads();

    for (int i = t; i < 4096; i += 256) cpa16(wsb + i*16, (const char*)out_w + i*16);
    cpa_commit();

    cpa_waitg<2>();
    __syncthreads();
    if (t < 128) {
        #pragma unroll
        for (int h = 0; h < 8; h++) {
            float s = 0.f;
            #pragma unroll
            for (int j = 0; j < 16; j++) s += W1[t*128 + h*16 + j]*q[h*16 + j];
            wkq[t*8 + h] = s;
        }
    }
    __syncthreads();

    if (t < 24) {
        int a = t/8, h = t%8;
        float s = 0.f;
        #pragma unroll 8
        for (int d = 0; d < 128; d++) s += lin_w[a*128+d]*wkq[d*8+h];
        g_score_w[a*8+h] = 0.25f*s;
    } else if (t < 32) {
        int h = t-24;
        float s = 0.f;
        #pragma unroll 8
        for (int d = 0; d < 128; d++) s += lb_s[d]*wkq[d*8+h];
        #pragma unroll
        for (int j = 0; j < 16; j++) s += q[h*16+j]*bk[h*16+j];
        g_score_c[h] = 0.25f*s;
    }

    cpa_waitg<1>();
    __syncthreads();
    if (t < 128) {
        float s0=0.f, s1=0.f, s2=0.f, sc=0.f;
        #pragma unroll 8
        for (int e = 0; e < 128; e++) {
            float w = Wv[e*128 + t];
            s0 += lin_w[0*128+e]*w;
            s1 += lin_w[1*128+e]*w;
            s2 += lin_w[2*128+e]*w;
            sc += lb_s[e]*w;
        }
        lwv[0*128+t]=s0; lwv[1*128+t]=s1; lwv[2*128+t]=s2;
        cv[t] = sc + bv[t];
    }
    cpa_waitg<0>();
    __syncthreads();
    if (t < 128) {
        #pragma unroll
        for (int h = 0; h < 8; h++)
            #pragma unroll
            for (int a = 0; a < 3; a++) {
                float s = 0.f;
                #pragma unroll
                for (int dd = 0; dd < 16; dd++) {
                    int d = h*16 + dd;
                    s += lwv[a*128+d]*W0[d*128+t];
                }
                g_W2[(h*3+a)*128 + t] = s;
            }
        float s = out_b[t];
        #pragma unroll 8
        for (int d = 0; d < 128; d++) s += cv[d]*W0[d*128+t];
        g_c2[t] = s;
    }
}

// ================= kernel 2: attention + LN1 + bf16 hi/lo emit (1 seg/warp) =================
__global__ void k_attn(const float* __restrict__ roads,
                       const float* __restrict__ ln1_g, const float* __restrict__ ln1_b,
                       float* __restrict__ d_out)
{
    const int n    = (blockIdx.x*blockDim.x + threadIdx.x) >> 5;
    const int lane = threadIdx.x & 31;
    if (n >= N_SEG) return;

    const float4* rp = reinterpret_cast<const float4*>(roads) + n*P_;
    float4 a0 = rp[lane];
    float4 a1 = make_float4(0.f,0.f,0.f,0.f);
    if (lane < 8) a1 = rp[32 + lane];

    bool v0 = (a0.w != 0.0f);
    bool v1 = (lane < 8) && (a1.w != 0.0f);
    unsigned bm0 = __ballot_sync(FULLMASK, v0);
    unsigned bm1 = __ballot_sync(FULLMASK, v1);
    const bool seg_empty = ((bm0 | bm1) == 0u);
    if (seg_empty && lane == 0) v0 = true;

    float pa[24];
    #pragma unroll
    for (int h = 0; h < 8; h++) {
        const float sw0 = __ldg(&g_score_w[0*8+h]);
        const float sw1 = __ldg(&g_score_w[1*8+h]);
        const float sw2 = __ldg(&g_score_w[2*8+h]);
        const float sc  = __ldg(&g_score_c[h]);
        float s0 = sc + a0.x*sw0 + a0.y*sw1 + a0.z*sw2;
        float s1 = sc + a1.x*sw0 + a1.y*sw1 + a1.z*sw2;
        float mx = fmaxf(v0 ? s0 : -1e30f, v1 ? s1 : -1e30f);
        #pragma unroll
        for (int o = 16; o; o >>= 1) mx = fmaxf(mx, __shfl_xor_sync(FULLMASK, mx, o));
        float e0 = v0 ? __expf(s0 - mx) : 0.0f;
        float e1 = v1 ? __expf(s1 - mx) : 0.0f;
        float t0 = e0 + e1;
        float t1 = e0*a0.x + e1*a1.x;
        float t2 = e0*a0.y + e1*a1.y;
        float t3 = e0*a0.z + e1*a1.z;
        #pragma unroll
        for (int o = 16; o; o >>= 1) {
            t0 += __shfl_xor_sync(FULLMASK, t0, o);
            t1 += __shfl_xor_sync(FULLMASK, t1, o);
            t2 += __shfl_xor_sync(FULLMASK, t2, o);
            t3 += __shfl_xor_sync(FULLMASK, t3, o);
        }
        float inv = 1.0f / t0;
        pa[h*3+0] = t1*inv;
        pa[h*3+1] = t2*inv;
        pa[h*3+2] = t3*inv;
    }

    float y[4];
    #pragma unroll
    for (int u = 0; u < 4; u++) {
        int j = lane + 32*u;
        float acc = __ldg(&g_c2[j]);
        #pragma unroll
        for (int i = 0; i < 24; i++) acc += pa[i]*__ldg(&g_W2[i*128 + j]);
        y[u] = acc;
    }

    float loc = y[0]+y[1]+y[2]+y[3];
    #pragma unroll
    for (int o = 16; o; o >>= 1) loc += __shfl_xor_sync(FULLMASK, loc, o);
    const float mu = loc * (1.0f/128.0f);
    float sq = 0.f;
    #pragma unroll
    for (int u = 0; u < 4; u++) { float d = y[u]-mu; sq += d*d; }
    #pragma unroll
    for (int o = 16; o; o >>= 1) sq += __shfl_xor_sync(FULLMASK, sq, o);
    const float istd = rsqrtf(sq*(1.0f/128.0f) + 1e-5f);
    #pragma unroll
    for (int u = 0; u < 4; u++) {
        int j = lane + 32*u;
        float e = (y[u]-mu)*istd*__ldg(&ln1_g[j]) + __ldg(&ln1_b[j]);
        g_emb[n*128 + j] = e;
        __nv_bfloat16 h = __float2bfloat16(e);
        g_embh[n*LDT + j] = h;
        g_embl[n*LDT + j] = __float2bfloat16(e - __bfloat162float(h));
    }

    if (lane == 0) d_out[OUT_ELEMS + n] = seg_empty ? 1.0f : 0.0f;
}

// ================= kernel 3: HMMA FFN, 96 rows/block, grid 134, warp tile m48 x n32 =================
// smem: AH | AL | HH | HL (4 x 26112) | BX | BY (2 x 34816) = 174080
#define K3_DSMEM (4*AT_B + 2*T_BYTES)

__device__ __forceinline__ void gemm_pass(uint32_t aB, uint32_t bB, float (&acc)[3][4][4])
{
    #pragma unroll
    for (int k = 0; k < 8; k++) {
        uint32_t a[3][4];
        #pragma unroll
        for (int mt = 0; mt < 3; mt++) ldsm4(a[mt], aB + mt*16*LDT*2 + k*32);
        #pragma unroll
        for (int ntp = 0; ntp < 2; ntp++) {
            uint32_t b[4];
            ldsm4(b, bB + ntp*16*LDT*2 + k*32);
            #pragma unroll
            for (int mt = 0; mt < 3; mt++) {
                mma16816(acc[mt][2*ntp+0], a[mt], b[0], b[1]);
                mma16816(acc[mt][2*ntp+1], a[mt], b[2], b[3]);
            }
        }
    }
}

__device__ __forceinline__ void stage_w(uint32_t dst, const __nv_bfloat16* src, int tid) {
    const char* s = reinterpret_cast<const char*>(src);
    for (int i = tid; i < T_BYTES/16; i += 256) cpa16(dst + i*16, s + i*16);
    cpa_commit();
}

__global__ __launch_bounds__(256, 1)
void k_ffn(const float* __restrict__ b1, const float* __restrict__ b2,
           const float* __restrict__ ln2_g, const float* __restrict__ ln2_b,
           float* __restrict__ d_out)
{
    extern __shared__ __align__(16) char smem[];
    __nv_bfloat16* sHh = reinterpret_cast<__nv_bfloat16*>(smem + 2*AT_B);
    __nv_bfloat16* sHl = reinterpret_cast<__nv_bfloat16*>(smem + 3*AT_B);

    const uint32_t sb = (uint32_t)__cvta_generic_to_shared(smem);
    const uint32_t AH = sb, AL = AH + AT_B, HH = AL + AT_B,
                   HL = HH + AT_B, BX = HL + AT_B, BY = BX + T_BYTES;

    const int tid  = threadIdx.x;
    const int wid  = tid >> 5;
    const int lane = tid & 31;
    const int qr   = lane >> 2;
    const int qc   = (lane & 3) << 1;
    const int mbase = (wid & 1) * 48;
    const int nbase = (wid >> 1) * 32;
    const int base  = blockIdx.x * ROWS;

    const uint32_t aoff = (uint32_t)(((lane & 15)*LDT + (lane >> 4)*8)*2 + mbase*LDT*2);
    const uint32_t boff = (uint32_t)((((lane & 7) + ((lane >> 4) << 3))*LDT
                                      + ((lane >> 3) & 1)*8)*2 + nbase*LDT*2);

    // ---- prologue: A(hi/lo) + W1(0) hi/lo, one cp.async group ----
    {
        const char* eh = reinterpret_cast<const char*>(g_embh + base*LDT);
        const char* el = reinterpret_cast<const char*>(g_embl + base*LDT);
        for (int i = tid; i < ROWS*16; i += 256) {
            int row = i >> 4, c = (i & 15) << 4;
            cpa16(AH + (uint32_t)(row*LDT*2) + c, eh + row*LDT*2 + c);
            cpa16(AL + (uint32_t)(row*LDT*2) + c, el + row*LDT*2 + c);
        }
        const char* s = reinterpret_cast<const char*>(g_wb);
        for (int i = tid; i < 2*T_BYTES/16; i += 256) cpa16(BX + i*16, s + i*16);
        cpa_commit();
    }

    // block 0: seg_mask all_seg fix (flags written by k_attn)
    if (blockIdx.x == 0 && tid < 128) {
        float allm = 1.0f;
        #pragma unroll 4
        for (int s = 0; s < S_; s++)
            allm = fminf(allm, d_out[OUT_ELEMS + tid*S_ + s]);
        if (allm > 0.5f) d_out[OUT_ELEMS + tid*S_] = 0.0f;
    }

    cpa_waitg<0>();
    __syncthreads();

    float acc2[3][4][4];
    #pragma unroll
    for (int mt = 0; mt < 3; mt++)
        #pragma unroll
        for (int nt = 0; nt < 4; nt++)
            #pragma unroll
            for (int c = 0; c < 4; c++) acc2[mt][nt][c] = 0.f;

    for (int kc = 0; kc < 3; kc++) {
        // entry: BX = W1hi(kc), BY = W1lo(kc)
        float acc1[3][4][4];
        #pragma unroll
        for (int mt = 0; mt < 3; mt++)
            #pragma unroll
            for (int nt = 0; nt < 4; nt++)
                #pragma unroll
                for (int c = 0; c < 4; c++) acc1[mt][nt][c] = 0.f;

        gemm_pass(AH + aoff, BX + boff, acc1);
        gemm_pass(AH + aoff, BY + boff, acc1);
        __syncthreads();                                   // BY free
        stage_w(BY, g_wb + (3+kc)*2*TILE_E, tid);          // W2hi(kc) -> BY
        gemm_pass(AL + aoff, BX + boff, acc1);

        // relu + bias + split -> H
        #pragma unroll
        for (int mt = 0; mt < 3; mt++)
            #pragma unroll
            for (int nt = 0; nt < 4; nt++) {
                const int row = mbase + mt*16 + qr;
                const int col = nbase + nt*8 + qc;
                const int cg  = kc*128 + col;
                float v0 = fmaxf(acc1[mt][nt][0] + __ldg(&b1[cg]),   0.f);
                float v1 = fmaxf(acc1[mt][nt][1] + __ldg(&b1[cg+1]), 0.f);
                float v2 = fmaxf(acc1[mt][nt][2] + __ldg(&b1[cg]),   0.f);
                float v3 = fmaxf(acc1[mt][nt][3] + __ldg(&b1[cg+1]), 0.f);
                *reinterpret_cast<uint32_t*>(sHh + row*LDT + col)     = pk2(v0, v1);
                *reinterpret_cast<uint32_t*>(sHl + row*LDT + col)     = pk2(blo(v0), blo(v1));
                *reinterpret_cast<uint32_t*>(sHh + (row+8)*LDT + col) = pk2(v2, v3);
                *reinterpret_cast<uint32_t*>(sHl + (row+8)*LDT + col) = pk2(blo(v2), blo(v3));
            }
        cpa_waitg<0>();
        __syncthreads();                                   // H + BY(W2hi) ready; BX free
        stage_w(BX, g_wb + ((3+kc)*2+1)*TILE_E, tid);      // W2lo(kc) -> BX
        gemm_pass(HH + aoff, BY + boff, acc2);
        cpa_waitg<0>();
        __syncthreads();                                   // BX(W2lo) ready
        gemm_pass(HH + aoff, BX + boff, acc2);
        gemm_pass(HL + aoff, BY + boff, acc2);

        if (kc < 2) {
            __syncthreads();                               // BX,BY free
            stage_w(BX, g_wb + (kc+1)*2*TILE_E, tid);      // W1hi(kc+1)
            stage_w(BY, g_wb + ((kc+1)*2+1)*TILE_E, tid);  // W1lo(kc+1)
            cpa_waitg<0>();
            __syncthreads();
        }
    }
    __syncthreads();

    // dump acc2 + bias + residual into fp32 smem [96][132]
    float* sF = reinterpret_cast<float*>(smem);
    #pragma unroll
    for (int mt = 0; mt < 3; mt++)
        #pragma unroll
        for (int nt = 0; nt < 4; nt++) {
            const int row = mbase + mt*16 + qr;
            const int col = nbase + nt*8 + qc;
            const float2 e0 = *reinterpret_cast<const float2*>(&g_emb[(base+row)*128 + col]);
            const float2 e1 = *reinterpret_cast<const float2*>(&g_emb[(base+row+8)*128 + col]);
            const float bb0 = __ldg(&b2[col]), bb1 = __ldg(&b2[col+1]);
            sF[row*132 + col]       = acc2[mt][nt][0] + bb0 + e0.x;
            sF[row*132 + col + 1]   = acc2[mt][nt][1] + bb1 + e0.y;
            sF[(row+8)*132 + col]   = acc2[mt][nt][2] + bb0 + e1.x;
            sF[(row+8)*132 + col+1] = acc2[mt][nt][3] + bb1 + e1.y;
        }
    __syncthreads();

    // LN2 + transposed store (2 threads per row, threads 0..191)
    if (tid < 2*ROWS) {
        const int row = tid >> 1;
        const int sub = tid & 1;
        const int n = base + row;
        if (n < N_SEG) {
            float sum = 0.f, sq = 0.f;
            #pragma unroll 8
            for (int c = sub*64; c < sub*64 + 64; c++) {
                float v = sF[row*132 + c];
                sum += v; sq += v*v;
            }
            sum += __shfl_xor_sync(FULLMASK, sum, 1);
            sq  += __shfl_xor_sync(FULLMASK, sq, 1);
            const float mu = sum * (1.0f/128.0f);
            const float istd = rsqrtf(sq*(1.0f/128.0f) - mu*mu + 1e-5f);

            const int s = n % S_;
            const int bm = n / S_;
            float* op = d_out + (((s*B_ + (bm >> 3))*M_ + (bm & 7)) << 7);
            #pragma unroll 4
            for (int c = sub*64; c < sub*64 + 64; c += 4) {
                float4 o4;
                o4.x = (sF[row*132+c+0]-mu)*istd*__ldg(&ln2_g[c+0]) + __ldg(&ln2_b[c+0]);
                o4.y = (sF[row*132+c+1]-mu)*istd*__ldg(&ln2_g[c+1]) + __ldg(&ln2_b[c+1]);
                o4.z = (sF[row*132+c+2]-mu)*istd*__ldg(&ln2_g[c+2]) + __ldg(&ln2_b[c+2]);
                o4.w = (sF[row*132+c+3]-mu)*istd*__ldg(&ln2_g[c+3]) + __ldg(&ln2_b[c+3]);
                *reinterpret_cast<float4*>(op + c) = o4;
            }
        }
    }
}

// ================= launcher =================
extern "C" void kernel_launch(void* const* d_in, const int* in_sizes, int n_in,
                              void* d_out, int out_size)
{
    const float* roads  = (const float*)d_in[0];
    const float* ms     = (const float*)d_in[2];
    const float* lin_w  = (const float*)d_in[3];
    const float* lin_b  = (const float*)d_in[4];
    const float* wq     = (const float*)d_in[5];
    const float* wk     = (const float*)d_in[6];
    const float* wv     = (const float*)d_in[7];
    const float* bq     = (const float*)d_in[8];
    const float* bk     = (const float*)d_in[9];
    const float* bv     = (const float*)d_in[10];
    const float* out_w  = (const float*)d_in[11];
    const float* out_b  = (const float*)d_in[12];
    const float* ln1_g  = (const float*)d_in[13];
    const float* ln1_b  = (const float*)d_in[14];
    const float* w1     = (const float*)d_in[15];
    const float* b1     = (const float*)d_in[16];
    const float* w2     = (const float*)d_in[17];
    const float* b2     = (const float*)d_in[18];
    const float* ln2_g  = (const float*)d_in[19];
    const float* ln2_b  = (const float*)d_in[20];
    float* out = (float*)d_out;

    cudaFuncSetAttribute(k_pre, cudaFuncAttributeMaxDynamicSharedMemorySize, PRE_DSMEM);
    cudaFuncSetAttribute(k_ffn, cudaFuncAttributeMaxDynamicSharedMemorySize, K3_DSMEM);

    k_pre<<<7, 256, PRE_DSMEM>>>(ms, lin_w, lin_b, wq, wk, wv, bq, bk, bv,
                                 out_w, out_b, w1, w2);
    k_attn<<<N_SEG/8, 256>>>(roads, ln1_g, ln1_b, out);
    k_ffn<<<NBLK, 256, K3_DSMEM>>>(b1, b2, ln2_g, ln2_b, out);
}